// round 7
// baseline (speedup 1.0000x reference)
#include <cuda_runtime.h>
#include <cuda_bf16.h>
#include <cstdint>
#include <float.h>

#define NN_  8192
#define DD_  1024
#define QQ_  4096
#define DK_  512
#define DV_  256
#define QB      64
#define NSPLIT  16
#define NTPC    4
#define SCALE_  0.044194173824159216f

typedef __nv_bfloat16 bf16;

// ---------------- scratch ----------------------------------------------------
__device__ bf16 g_Xhi [(size_t)NN_*DD_], g_Xlo [(size_t)NN_*DD_];
__device__ bf16 g_Qhi [(size_t)QQ_*DD_], g_Qlo [(size_t)QQ_*DD_];
__device__ bf16 g_WkThi[(size_t)DK_*DD_], g_WkTlo[(size_t)DK_*DD_];
__device__ bf16 g_WqThi[(size_t)DK_*DD_], g_WqTlo[(size_t)DK_*DD_];
__device__ bf16 g_Khi [(size_t)NN_*DK_], g_Klo [(size_t)NN_*DK_];
__device__ bf16 g_QKhi[(size_t)QQ_*DK_], g_QKlo[(size_t)QQ_*DK_];
__device__ bf16 g_yThi[(size_t)DV_*NN_], g_yTlo[(size_t)DV_*NN_];
__device__ float g_O  [(size_t)NSPLIT*QQ_*DV_];
__device__ float g_M  [(size_t)NSPLIT*QQ_];
__device__ float g_Lr [(size_t)NSPLIT*QQ_];
__device__ int   g_is64;

// ---------------- base-ISA helpers -------------------------------------------
__device__ __forceinline__ uint32_t smem_to_u32(const void* p) {
    uint32_t a;
    asm("{ .reg .u64 t; cvta.to.shared.u64 t, %1; cvt.u32.u64 %0, t; }"
        : "=r"(a) : "l"(p));
    return a;
}
__device__ __forceinline__ void cp_async16(uint32_t dst, const void* src) {
    asm volatile("cp.async.cg.shared.global [%0], [%1], 16;" :: "r"(dst), "l"(src));
}
#define CP_COMMIT() asm volatile("cp.async.commit_group;" ::: "memory")
template<int N> __device__ __forceinline__ void cp_wait() {
    asm volatile("cp.async.wait_group %0;" :: "n"(N) : "memory");
}
__device__ __forceinline__ void ldm_x4(uint32_t* r, uint32_t addr) {
    asm volatile("ldmatrix.sync.aligned.m8n8.x4.shared.b16 {%0,%1,%2,%3}, [%4];"
        : "=r"(r[0]), "=r"(r[1]), "=r"(r[2]), "=r"(r[3]) : "r"(addr));
}
__device__ __forceinline__ void mma_bf16(float* c, const uint32_t* a,
                                         uint32_t b0, uint32_t b1) {
    asm volatile(
        "mma.sync.aligned.m16n8k16.row.col.f32.bf16.bf16.f32 "
        "{%0,%1,%2,%3}, {%4,%5,%6,%7}, {%8,%9}, {%0,%1,%2,%3};"
        : "+f"(c[0]), "+f"(c[1]), "+f"(c[2]), "+f"(c[3])
        : "r"(a[0]), "r"(a[1]), "r"(a[2]), "r"(a[3]), "r"(b0), "r"(b1));
}

// ---------------- fused projection GEMM (keys + qk in one launch) -------------
#define SK      40
#define TILEB   (128 * SK * 2)
#define STAGE_B (4 * TILEB)
#define PROJ_SMEM (2 * STAGE_B)

__device__ __forceinline__ void load_tile32p(uint32_t sb32, const bf16* __restrict__ g,
                                             int ldg, int tid)
{
    #pragma unroll
    for (int it = 0; it < 2; it++) {
        int idx = it * 256 + tid;
        int row = idx >> 2, ch = idx & 3;
        cp_async16(sb32 + (uint32_t)(row * SK + ch * 8) * 2,
                   g + (size_t)row * ldg + ch * 8);
    }
}

__global__ __launch_bounds__(256)
void proj_gemm(const bf16* __restrict__ Xhi, const bf16* __restrict__ Xlo,
               const bf16* __restrict__ WkThi, const bf16* __restrict__ WkTlo,
               bf16* __restrict__ Khi, bf16* __restrict__ Klo,
               const bf16* __restrict__ Qhi, const bf16* __restrict__ Qlo,
               const bf16* __restrict__ WqThi, const bf16* __restrict__ WqTlo,
               bf16* __restrict__ QKhi, bf16* __restrict__ QKlo)
{
    extern __shared__ char smem[];
    const int tid  = threadIdx.x;
    const int lane = tid & 31;
    const int w    = tid >> 5;
    const int bn   = blockIdx.x * 128;
    const int wm   = (w & 1) * 64;
    const int wn   = (w >> 1) * 32;
    const uint32_t s32 = smem_to_u32(smem);

    const bf16 *Ahi, *Alo, *Bhi, *Blo;
    bf16 *Chi, *Clo;
    int bm;
    if (blockIdx.y < NN_/128) {
        bm = blockIdx.y * 128;
        Ahi = Xhi; Alo = Xlo; Bhi = WkThi; Blo = WkTlo; Chi = Khi; Clo = Klo;
    } else {
        bm = (blockIdx.y - NN_/128) * 128;
        Ahi = Qhi; Alo = Qlo; Bhi = WqThi; Blo = WqTlo; Chi = QKhi; Clo = QKlo;
    }
    const bf16* gAh = Ahi + (size_t)bm * DD_;
    const bf16* gAl = Alo + (size_t)bm * DD_;
    const bf16* gBh = Bhi + (size_t)bn * DD_;
    const bf16* gBl = Blo + (size_t)bn * DD_;

    float acc[4][4][4];
    #pragma unroll
    for (int i = 0; i < 4; i++)
        #pragma unroll
        for (int j = 0; j < 4; j++)
            #pragma unroll
            for (int r = 0; r < 4; r++) acc[i][j][r] = 0.f;

    load_tile32p(s32 + 0*TILEB, gAh, DD_, tid);
    load_tile32p(s32 + 1*TILEB, gAl, DD_, tid);
    load_tile32p(s32 + 2*TILEB, gBh, DD_, tid);
    load_tile32p(s32 + 3*TILEB, gBl, DD_, tid);
    CP_COMMIT();

    const int lr = lane & 15;
    const int lc = (lane >> 4) * 8;
    const int nkb = DD_ / 32;

    for (int kb = 0; kb < nkb; kb++) {
        if (kb + 1 < nkb) {
            uint32_t b = s32 + ((kb + 1) & 1) * STAGE_B;
            const size_t ko = (size_t)(kb + 1) * 32;
            load_tile32p(b + 0*TILEB, gAh + ko, DD_, tid);
            load_tile32p(b + 1*TILEB, gAl + ko, DD_, tid);
            load_tile32p(b + 2*TILEB, gBh + ko, DD_, tid);
            load_tile32p(b + 3*TILEB, gBl + ko, DD_, tid);
            CP_COMMIT();
            cp_wait<1>();
        } else {
            cp_wait<0>();
        }
        __syncthreads();
        const uint32_t base = s32 + (kb & 1) * STAGE_B;
        #pragma unroll
        for (int ki = 0; ki < 2; ki++) {
            uint32_t ah[4][4], al[4][4], bh[2][4], bl[2][4];
            #pragma unroll
            for (int im = 0; im < 4; im++) {
                uint32_t off = (uint32_t)((wm + im*16 + lr) * SK + ki*16 + lc) * 2;
                ldm_x4(ah[im], base + 0*TILEB + off);
                ldm_x4(al[im], base + 1*TILEB + off);
            }
            #pragma unroll
            for (int g = 0; g < 2; g++) {
                uint32_t off = (uint32_t)((wn + g*16 + lr) * SK + ki*16 + lc) * 2;
                ldm_x4(bh[g], base + 2*TILEB + off);
                ldm_x4(bl[g], base + 3*TILEB + off);
            }
            #pragma unroll
            for (int im = 0; im < 4; im++)
                #pragma unroll
                for (int in = 0; in < 4; in++) {
                    const int i2 = in >> 1, s = in & 1;
                    mma_bf16(acc[im][in], ah[im], bh[i2][s], bh[i2][2+s]);
                    mma_bf16(acc[im][in], ah[im], bl[i2][s], bl[i2][2+s]);
                    mma_bf16(acc[im][in], al[im], bh[i2][s], bh[i2][2+s]);
                }
        }
        __syncthreads();
    }

    const int er = lane >> 2;
    const int ec = (lane & 3) * 2;
    #pragma unroll
    for (int im = 0; im < 4; im++)
        #pragma unroll
        for (int in = 0; in < 4; in++) {
            const int row0 = bm + wm + im*16 + er;
            const int col  = bn + wn + in*8 + ec;
            #pragma unroll
            for (int h = 0; h < 2; h++) {
                const size_t off = (size_t)(row0 + h*8) * DK_ + col;
                float v0 = acc[im][in][2*h + 0];
                float v1 = acc[im][in][2*h + 1];
                bf16 h0 = __float2bfloat16(v0);
                bf16 h1 = __float2bfloat16(v1);
                bf16 l0 = __float2bfloat16(v0 - __bfloat162float(h0));
                bf16 l1 = __float2bfloat16(v1 - __bfloat162float(h1));
                *reinterpret_cast<__nv_bfloat162*>(Chi + off) = __nv_bfloat162(h0, h1);
                *reinterpret_cast<__nv_bfloat162*>(Clo + off) = __nv_bfloat162(l0, l1);
            }
        }
}

// ---------------- fused flash attention --------------------------------------
#define STG        40960
#define OFF_P      (2*STG)
#define P_LO       17408
#define OFF_MASK   (OFF_P + 2*P_LO)
#define OFF_STATS  (OFF_MASK + 65536)
#define FLASH_SMEM (OFF_STATS + 2048)
#define SKP        136

__global__ __launch_bounds__(256)
void flash_kernel(const bf16* __restrict__ QKhi, const bf16* __restrict__ QKlo,
                  const bf16* __restrict__ Khi,  const bf16* __restrict__ Klo,
                  const bf16* __restrict__ yThi, const bf16* __restrict__ yTlo,
                  const char* __restrict__ maskp,
                  float* __restrict__ Opart, float* __restrict__ Mpart,
                  float* __restrict__ Lpart)
{
    extern __shared__ char smem[];
    const int tid  = threadIdx.x;
    const int lane = tid & 31;
    const int w    = tid >> 5;
    const int wqm  = (w & 1) * 32;
    const int wsn  = (w >> 1) * 32;
    const int wvn  = (w >> 1) * 64;
    const int z    = blockIdx.x;
    const int qbase = blockIdx.y * QB;
    const int is64 = g_is64;
    const uint32_t s32 = smem_to_u32(smem);

    float* m_state = reinterpret_cast<float*>(smem + OFF_STATS);
    float* l_state = m_state + 64;
    float* alpha_s = l_state + 64;
    float* mrow    = alpha_s + 64;
    float* red     = mrow + 64;   // [4][64]

    if (tid < 64) { m_state[tid] = -FLT_MAX; l_state[tid] = 0.f; }
    __syncthreads();

    float oacc[2][8][4];
    #pragma unroll
    for (int mi = 0; mi < 2; mi++)
        #pragma unroll
        for (int ni = 0; ni < 8; ni++)
            #pragma unroll
            for (int r = 0; r < 4; r++) oacc[mi][ni][r] = 0.f;

    const int lr = lane & 15;
    const int lc = (lane >> 4) * 8;
    const int er = lane >> 2;
    const int ec = (lane & 3) * 2;

    for (int nt = 0; nt < NTPC; nt++) {
        const int nbase = z * (NN_/NSPLIT) + nt * 128;

        // mask tile (own async group; completes by end of phase 1)
        if (is64) {
            #pragma unroll
            for (int o = 0; o < 16; o++) {
                int id = o * 256 + tid;
                int row = id >> 6, b = id & 63;
                cp_async16(s32 + OFF_MASK + row * 1024 + b * 16,
                           maskp + ((size_t)(qbase + row) * NN_ + nbase) * 8 + b * 16);
            }
        } else {
            #pragma unroll
            for (int o = 0; o < 8; o++) {
                int id = o * 256 + tid;
                int row = id >> 5, b = id & 31;
                cp_async16(s32 + OFF_MASK + row * 512 + b * 16,
                           maskp + ((size_t)(qbase + row) * NN_ + nbase) * 4 + b * 16);
            }
        }
        CP_COMMIT();

        auto load_s = [&](int kb, int buf) {
            uint32_t base = s32 + buf * STG;
            const int k0 = kb * 32;
            {
                int row = tid >> 2, ch = tid & 3;
                uint32_t o = (uint32_t)(row * SK + ch * 8) * 2;
                cp_async16(base + o,        QKhi + (size_t)(qbase + row) * DK_ + k0 + ch * 8);
                cp_async16(base + 5120 + o, QKlo + (size_t)(qbase + row) * DK_ + k0 + ch * 8);
            }
            #pragma unroll
            for (int o2 = 0; o2 < 2; o2++) {
                int id = o2 * 256 + tid;
                int row = id >> 2, ch = id & 3;
                uint32_t o = (uint32_t)(row * SK + ch * 8) * 2;
                cp_async16(base + 10240 + o, Khi + (size_t)(nbase + row) * DK_ + k0 + ch * 8);
                cp_async16(base + 20480 + o, Klo + (size_t)(nbase + row) * DK_ + k0 + ch * 8);
            }
        };
        auto load_y = [&](int kc, int buf) {
            uint32_t base = s32 + buf * STG;
            #pragma unroll
            for (int o2 = 0; o2 < 4; o2++) {
                int id = o2 * 256 + tid;
                int row = id >> 2, ch = id & 3;
                uint32_t o = (uint32_t)(row * SK + ch * 8) * 2;
                cp_async16(base + o,         yThi + (size_t)row * NN_ + nbase + kc*32 + ch*8);
                cp_async16(base + 20480 + o, yTlo + (size_t)row * NN_ + nbase + kc*32 + ch*8);
            }
        };

        // ---- phase 1: S = QK · K^T
        float sacc[2][4][4];
        #pragma unroll
        for (int mi = 0; mi < 2; mi++)
            #pragma unroll
            for (int ni = 0; ni < 4; ni++)
                #pragma unroll
                for (int r = 0; r < 4; r++) sacc[mi][ni][r] = 0.f;

        load_s(0, 0); CP_COMMIT();
        for (int kb = 0; kb < 16; kb++) {
            if (kb < 15) { load_s(kb + 1, (kb + 1) & 1); CP_COMMIT(); cp_wait<1>(); }
            else         { cp_wait<0>(); }
            __syncthreads();
            const uint32_t base = s32 + (kb & 1) * STG;
            #pragma unroll
            for (int ki = 0; ki < 2; ki++) {
                uint32_t ah[2][4], al[2][4], bh[2][4], bl[2][4];
                #pragma unroll
                for (int mi = 0; mi < 2; mi++) {
                    uint32_t off = (uint32_t)((wqm + mi*16 + lr) * SK + ki*16 + lc) * 2;
                    ldm_x4(ah[mi], base + off);
                    ldm_x4(al[mi], base + 5120 + off);
                }
                #pragma unroll
                for (int g = 0; g < 2; g++) {
                    uint32_t off = (uint32_t)((wsn + g*16 + lr) * SK + ki*16 + lc) * 2;
                    ldm_x4(bh[g], base + 10240 + off);
                    ldm_x4(bl[g], base + 20480 + off);
                }
                #pragma unroll
                for (int mi = 0; mi < 2; mi++)
                    #pragma unroll
                    for (int ni = 0; ni < 4; ni++) {
                        const int g = ni >> 1, s = ni & 1;
                        mma_bf16(sacc[mi][ni], ah[mi], bh[g][s], bh[g][2+s]);
                        mma_bf16(sacc[mi][ni], ah[mi], bl[g][s], bl[g][2+s]);
                        mma_bf16(sacc[mi][ni], al[mi], bh[g][s], bh[g][2+s]);
                    }
            }
            __syncthreads();
        }

        load_y(0, 0); CP_COMMIT();   // prefetch y chunk 0 behind softmax

        // ---- softmax pass 1: mask bits + row max
        uint32_t bits = 0;
        float rmax[2][2] = {{-FLT_MAX, -FLT_MAX}, {-FLT_MAX, -FLT_MAX}};
        #pragma unroll
        for (int mi = 0; mi < 2; mi++)
            #pragma unroll
            for (int ni = 0; ni < 4; ni++)
                #pragma unroll
                for (int r = 0; r < 4; r++) {
                    int row = wqm + mi*16 + er + (r >> 1) * 8;
                    int col = wsn + ni*8 + ec + (r & 1);
                    uint32_t mv = is64
                        ? *reinterpret_cast<const uint32_t*>(smem + OFF_MASK + (row*128 + col)*8)
                        : *reinterpret_cast<const uint32_t*>(smem + OFF_MASK + (row*128 + col)*4);
                    if (mv) {
                        bits |= 1u << (mi*16 + ni*4 + r);
                        float v = sacc[mi][ni][r] * SCALE_;
                        rmax[mi][r >> 1] = fmaxf(rmax[mi][r >> 1], v);
                    }
                }
        #pragma unroll
        for (int mi = 0; mi < 2; mi++)
            #pragma unroll
            for (int h = 0; h < 2; h++) {
                float v = rmax[mi][h];
                v = fmaxf(v, __shfl_xor_sync(0xFFFFFFFFu, v, 1));
                v = fmaxf(v, __shfl_xor_sync(0xFFFFFFFFu, v, 2));
                if ((lane & 3) == 0)
                    red[(w >> 1) * 64 + wqm + mi*16 + h*8 + er] = v;
            }
        __syncthreads();
        if (tid < 64) {
            float mt = fmaxf(fmaxf(red[tid], red[64 + tid]),
                             fmaxf(red[128 + tid], red[192 + tid]));
            float mnew = fmaxf(m_state[tid], mt);
            alpha_s[tid] = __expf(m_state[tid] - mnew);
            m_state[tid] = mnew;
            mrow[tid]    = mnew;
        }
        __syncthreads();

        // ---- pass 2: exp, P->smem hi/lo, O rescale, row sums
        #pragma unroll
        for (int mi = 0; mi < 2; mi++)
            #pragma unroll
            for (int h = 0; h < 2; h++) {
                const int row = wqm + mi*16 + er + h*8;
                const float m = mrow[row];
                const float a = alpha_s[row];
                float rsum = 0.f;
                #pragma unroll
                for (int ni = 0; ni < 4; ni++) {
                    const int idx0 = mi*16 + ni*4 + h*2;
                    float p0 = 0.f, p1 = 0.f;
                    if (bits & (1u << idx0))
                        p0 = __expf(sacc[mi][ni][h*2 + 0] * SCALE_ - m);
                    if (bits & (1u << (idx0 + 1)))
                        p1 = __expf(sacc[mi][ni][h*2 + 1] * SCALE_ - m);
                    rsum += p0 + p1;
                    bf16 h0 = __float2bfloat16(p0);
                    bf16 h1 = __float2bfloat16(p1);
                    bf16 l0 = __float2bfloat16(p0 - __bfloat162float(h0));
                    bf16 l1 = __float2bfloat16(p1 - __bfloat162float(h1));
                    const int pcol = wsn + ni*8 + ec;
                    *reinterpret_cast<__nv_bfloat162*>(
                        smem + OFF_P + (row * SKP + pcol) * 2) = __nv_bfloat162(h0, h1);
                    *reinterpret_cast<__nv_bfloat162*>(
                        smem + OFF_P + P_LO + (row * SKP + pcol) * 2) = __nv_bfloat162(l0, l1);
                }
                #pragma unroll
                for (int ni = 0; ni < 8; ni++) {
                    oacc[mi][ni][h*2 + 0] *= a;
                    oacc[mi][ni][h*2 + 1] *= a;
                }
                rsum += __shfl_xor_sync(0xFFFFFFFFu, rsum, 1);
                rsum += __shfl_xor_sync(0xFFFFFFFFu, rsum, 2);
                if ((lane & 3) == 0) red[(w >> 1) * 64 + row] = rsum;
            }
        __syncthreads();
        if (tid < 64)
            l_state[tid] = l_state[tid] * alpha_s[tid] +
                           red[tid] + red[64 + tid] + red[128 + tid] + red[192 + tid];

        // ---- phase 3: O += P · y
        for (int kc = 0; kc < 4; kc++) {
            if (kc < 3) { load_y(kc + 1, (kc + 1) & 1); CP_COMMIT(); cp_wait<1>(); }
            else        { cp_wait<0>(); }
            __syncthreads();
            const uint32_t ybase = s32 + (kc & 1) * STG;
            #pragma unroll
            for (int ki = 0; ki < 2; ki++) {
                uint32_t ph[2][4], pl[2][4], yh[4][4], yl[4][4];
                #pragma unroll
                for (int mi = 0; mi < 2; mi++) {
                    uint32_t off = (uint32_t)((wqm + mi*16 + lr) * SKP + kc*32 + ki*16 + lc) * 2;
                    ldm_x4(ph[mi], s32 + OFF_P + off);
                    ldm_x4(pl[mi], s32 + OFF_P + P_LO + off);
                }
                #pragma unroll
                for (int g = 0; g < 4; g++) {
                    uint32_t off = (uint32_t)((wvn + g*16 + lr) * SK + ki*16 + lc) * 2;
                    ldm_x4(yh[g], ybase + off);
                    ldm_x4(yl[g], ybase + 20480 + off);
                }
                #pragma unroll
                for (int mi = 0; mi < 2; mi++)
                    #pragma unroll
                    for (int ni = 0; ni < 8; ni++) {
                        const int g = ni >> 1, s = ni & 1;
                        mma_bf16(oacc[mi][ni], ph[mi], yh[g][s], yh[g][2+s]);
                        mma_bf16(oacc[mi][ni], ph[mi], yl[g][s], yl[g][2+s]);
                        mma_bf16(oacc[mi][ni], pl[mi], yh[g][s], yh[g][2+s]);
                    }
            }
            __syncthreads();
        }
    }

    float* Op = Opart + ((size_t)z * QQ_ + qbase) * DV_;
    #pragma unroll
    for (int mi = 0; mi < 2; mi++)
        #pragma unroll
        for (int ni = 0; ni < 8; ni++) {
            const int row = wqm + mi*16 + er;
            const int col = wvn + ni*8 + ec;
            float2 v0 = {oacc[mi][ni][0], oacc[mi][ni][1]};
            float2 v1 = {oacc[mi][ni][2], oacc[mi][ni][3]};
            *reinterpret_cast<float2*>(Op + (size_t)row * DV_ + col)       = v0;
            *reinterpret_cast<float2*>(Op + (size_t)(row + 8) * DV_ + col) = v1;
        }
    if (tid < 64) {
        Mpart[(size_t)z * QQ_ + qbase + tid] = m_state[tid];
        Lpart[(size_t)z * QQ_ + qbase + tid] = l_state[tid];
    }
}

// ---------------- combine ----------------------------------------------------
__global__ __launch_bounds__(256)
void combine_kernel(const float* __restrict__ Opart, const float* __restrict__ Mpart,
                    const float* __restrict__ Lpart, float* __restrict__ out)
{
    int gid = blockIdx.x * 256 + threadIdx.x;
    if (gid >= QQ_ * (DV_ / 4)) return;
    const int q  = gid / (DV_ / 4);
    const int c4 = (gid % (DV_ / 4)) * 4;

    float mmax = -FLT_MAX;
    #pragma unroll
    for (int zz = 0; zz < NSPLIT; zz++)
        mmax = fmaxf(mmax, Mpart[(size_t)zz * QQ_ + q]);

    float4 acc = {0.f, 0.f, 0.f, 0.f};
    float den = 0.f;
    #pragma unroll
    for (int zz = 0; zz < NSPLIT; zz++) {
        float wz = __expf(Mpart[(size_t)zz * QQ_ + q] - mmax);
        den += wz * Lpart[(size_t)zz * QQ_ + q];
        float4 v = *reinterpret_cast<const float4*>(
            Opart + ((size_t)zz * QQ_ + q) * DV_ + c4);
        acc.x += wz * v.x; acc.y += wz * v.y;
        acc.z += wz * v.z; acc.w += wz * v.w;
    }
    float inv = (den > 0.f) ? (1.f / den) : 0.f;
    acc.x *= inv; acc.y *= inv; acc.z *= inv; acc.w *= inv;
    *reinterpret_cast<float4*>(out + (size_t)q * DV_ + c4) = acc;
}

// ---------------- prep kernels -----------------------------------------------
__global__ void detect_mask_kernel(const unsigned int* __restrict__ mw)
{
    __shared__ int any;
    if (threadIdx.x == 0) any = 0;
    __syncthreads();
    int local = 0;
    for (int i = threadIdx.x; i < 4096; i += blockDim.x)
        if (mw[2 * i + 1] != 0u) local = 1;
    if (local) atomicOr(&any, 1);
    __syncthreads();
    if (threadIdx.x == 0) g_is64 = any ? 0 : 1;
}

__global__ __launch_bounds__(256)
void split_both_kernel(const float* __restrict__ X, const float* __restrict__ Qx,
                       bf16* __restrict__ Xhi, bf16* __restrict__ Xlo,
                       bf16* __restrict__ Qhi, bf16* __restrict__ Qlo)
{
    const int n4X = NN_ * DD_ / 4;
    const int n4Q = QQ_ * DD_ / 4;
    int i = blockIdx.x * 256 + threadIdx.x;
    const float* src; bf16 *hi, *lo; int j;
    if (i < n4X)            { src = X;  hi = Xhi; lo = Xlo; j = i; }
    else if (i < n4X + n4Q) { src = Qx; hi = Qhi; lo = Qlo; j = i - n4X; }
    else return;
    float4 v = reinterpret_cast<const float4*>(src)[j];
    float f[4] = {v.x, v.y, v.z, v.w};
    bf16 h[4], l[4];
    #pragma unroll
    for (int k = 0; k < 4; k++) {
        h[k] = __float2bfloat16(f[k]);
        l[k] = __float2bfloat16(f[k] - __bfloat162float(h[k]));
    }
    reinterpret_cast<__nv_bfloat162*>(hi)[2*j+0] = __nv_bfloat162(h[0], h[1]);
    reinterpret_cast<__nv_bfloat162*>(hi)[2*j+1] = __nv_bfloat162(h[2], h[3]);
    reinterpret_cast<__nv_bfloat162*>(lo)[2*j+0] = __nv_bfloat162(l[0], l[1]);
    reinterpret_cast<__nv_bfloat162*>(lo)[2*j+1] = __nv_bfloat162(l[2], l[3]);
}

// out[c*R + r] = in[r*C + c]; z picks (Wk, Wq)
__global__ __launch_bounds__(256)
void transpose_W_kernel(const float* __restrict__ Wk, const float* __restrict__ Wq,
                        bf16* __restrict__ WkThi, bf16* __restrict__ WkTlo,
                        bf16* __restrict__ WqThi, bf16* __restrict__ WqTlo)
{
    __shared__ float tile[32][33];
    const float* in = blockIdx.z ? Wq : Wk;
    bf16* hi = blockIdx.z ? WqThi : WkThi;
    bf16* lo = blockIdx.z ? WqTlo : WkTlo;
    const int R = DD_, C = DK_;
    const int cb = blockIdx.x * 32, rb = blockIdx.y * 32;
    const int tx = threadIdx.x & 31, ty0 = threadIdx.x >> 5;
    #pragma unroll
    for (int i = 0; i < 4; i++) {
        int ty = ty0 + i * 8;
        tile[ty][tx] = in[(size_t)(rb + ty) * C + cb + tx];
    }
    __syncthreads();
    #pragma unroll
    for (int i = 0; i < 4; i++) {
        int ty = ty0 + i * 8;
        float v = tile[tx][ty];
        bf16 h = __float2bfloat16(v);
        bf16 l = __float2bfloat16(v - __bfloat162float(h));
        size_t o = (size_t)(cb + ty) * R + rb + tx;
        hi[o] = h; lo[o] = l;
    }
}

__global__ __launch_bounds__(256)
void transpose_y_kernel(const float* __restrict__ in,
                        bf16* __restrict__ hi, bf16* __restrict__ lo)
{
    __shared__ float tile[32][33];
    const int R = NN_, C = DV_;
    const int cb = blockIdx.x * 32, rb = blockIdx.y * 32;
    const int tx = threadIdx.x & 31, ty0 = threadIdx.x >> 5;
    #pragma unroll
    for (int i = 0; i < 4; i++) {
        int ty = ty0 + i * 8;
        tile[ty][tx] = in[(size_t)(rb + ty) * C + cb + tx];
    }
    __syncthreads();
    #pragma unroll
    for (int i = 0; i < 4; i++) {
        int ty = ty0 + i * 8;
        float v = tile[tx][ty];
        bf16 h = __float2bfloat16(v);
        bf16 l = __float2bfloat16(v - __bfloat162float(h));
        size_t o = (size_t)(cb + ty) * R + rb + tx;
        hi[o] = h; lo[o] = l;
    }
}

// ---------------- launch ----------------------------------------------------
extern "C" void kernel_launch(void* const* d_in, const int* in_sizes, int n_in,
                              void* d_out, int out_size)
{
    const float* search_x = nullptr;
    const float* search_y = nullptr;
    const float* query_x  = nullptr;
    const unsigned int* maskw = nullptr;
    const float* Wk = nullptr;
    const float* Wq = nullptr;

    for (int i = 0; i < n_in; i++) {
        long long sz = in_sizes[i];
        if      (sz == (long long)NN_ * DD_)  search_x = (const float*)d_in[i];
        else if (sz == (long long)NN_ * DV_)  search_y = (const float*)d_in[i];
        else if (sz == (long long)QQ_ * DD_)  query_x  = (const float*)d_in[i];
        else if (sz == (long long)QQ_ * NN_)  maskw    = (const unsigned int*)d_in[i];
        else if (sz == (long long)DD_ * DK_) { if (!Wk) Wk = (const float*)d_in[i];
                                               else      Wq = (const float*)d_in[i]; }
    }
    float* out = (float*)d_out;

    bf16 *Xhi,*Xlo,*Qhi,*Qlo,*WkThi,*WkTlo,*WqThi,*WqTlo;
    bf16 *Khi,*Klo,*QKhi,*QKlo,*yThi,*yTlo;
    float *Op, *Mp, *Lrp;
    cudaGetSymbolAddress((void**)&Xhi,  g_Xhi);  cudaGetSymbolAddress((void**)&Xlo,  g_Xlo);
    cudaGetSymbolAddress((void**)&Qhi,  g_Qhi);  cudaGetSymbolAddress((void**)&Qlo,  g_Qlo);
    cudaGetSymbolAddress((void**)&WkThi,g_WkThi);cudaGetSymbolAddress((void**)&WkTlo,g_WkTlo);
    cudaGetSymbolAddress((void**)&WqThi,g_WqThi);cudaGetSymbolAddress((void**)&WqTlo,g_WqTlo);
    cudaGetSymbolAddress((void**)&Khi,  g_Khi);  cudaGetSymbolAddress((void**)&Klo,  g_Klo);
    cudaGetSymbolAddress((void**)&QKhi, g_QKhi); cudaGetSymbolAddress((void**)&QKlo, g_QKlo);
    cudaGetSymbolAddress((void**)&yThi, g_yThi); cudaGetSymbolAddress((void**)&yTlo, g_yTlo);
    cudaGetSymbolAddress((void**)&Op,   g_O);    cudaGetSymbolAddress((void**)&Mp,   g_M);
    cudaGetSymbolAddress((void**)&Lrp,  g_Lr);

    cudaFuncSetAttribute(proj_gemm,
        cudaFuncAttributeMaxDynamicSharedMemorySize, PROJ_SMEM);
    cudaFuncSetAttribute(flash_kernel,
        cudaFuncAttributeMaxDynamicSharedMemorySize, FLASH_SMEM);

    // 1) mask probe
    detect_mask_kernel<<<1, 256>>>(maskw);
    // 2) split X and Q
    split_both_kernel<<<((NN_+QQ_)*DD_/4 + 255)/256, 256>>>(
        search_x, query_x, Xhi, Xlo, Qhi, Qlo);
    // 3) transpose+split W (both in one launch)
    transpose_W_kernel<<<dim3(DK_/32, DD_/32, 2), 256>>>(
        Wk, Wq, WkThi, WkTlo, WqThi, WqTlo);
    // 4) transpose+split y
    transpose_y_kernel<<<dim3(DV_/32, NN_/32), 256>>>(search_y, yThi, yTlo);
    // 5) fused projections: keys & qk
    proj_gemm<<<dim3(DK_/128, NN_/128 + QQ_/128), 256, PROJ_SMEM>>>(
        Xhi, Xlo, WkThi, WkTlo, Khi, Klo,
        Qhi, Qlo, WqThi, WqTlo, QKhi, QKlo);
    // 6) fused flash attention (profiled launch)
    flash_kernel<<<dim3(NSPLIT, QQ_/QB), 256, FLASH_SMEM>>>(
        QKhi, QKlo, Khi, Klo, yThi, yTlo,
        (const char*)maskw, Op, Mp, Lrp);
    // 7) combine partials
    combine_kernel<<<(QQ_*DV_/4 + 255)/256, 256>>>(Op, Mp, Lrp, out);

    (void)out_size; (void)n_in;
}

// round 8
// speedup vs baseline: 1.6922x; 1.6922x over previous
#include <cuda_runtime.h>
#include <cuda_fp16.h>
#include <cstdint>
#include <float.h>

#define NN_  8192
#define DD_  1024
#define QQ_  4096
#define DK_  512
#define DV_  256
#define KSPLIT_PV 16
#define SCALE_  0.044194173824159216f

typedef __half h16;

// ---------------- scratch ----------------------------------------------------
__device__ h16 g_Xhi [(size_t)NN_*DD_], g_Xlo [(size_t)NN_*DD_];
__device__ h16 g_Qhi [(size_t)QQ_*DD_], g_Qlo [(size_t)QQ_*DD_];
__device__ h16 g_WkTh[(size_t)DK_*DD_];
__device__ h16 g_WqTh[(size_t)DK_*DD_];
__device__ h16 g_Kh  [(size_t)NN_*DK_];
__device__ h16 g_QKh [(size_t)QQ_*DK_], g_QKl[(size_t)QQ_*DK_];
__device__ float g_L [(size_t)QQ_*NN_];
__device__ h16 g_Ph  [(size_t)QQ_*NN_];
__device__ h16 g_yTh [(size_t)DV_*NN_];
__device__ float g_part[(size_t)KSPLIT_PV*QQ_*DV_];
__device__ int   g_is64;

// ---------------- base-ISA helpers -------------------------------------------
__device__ __forceinline__ uint32_t smem_to_u32(const void* p) {
    uint32_t a;
    asm("{ .reg .u64 t; cvta.to.shared.u64 t, %1; cvt.u32.u64 %0, t; }"
        : "=r"(a) : "l"(p));
    return a;
}
__device__ __forceinline__ void cp_async16(uint32_t dst, const void* src) {
    asm volatile("cp.async.cg.shared.global [%0], [%1], 16;" :: "r"(dst), "l"(src));
}
#define CP_COMMIT() asm volatile("cp.async.commit_group;" ::: "memory")
template<int N> __device__ __forceinline__ void cp_wait() {
    asm volatile("cp.async.wait_group %0;" :: "n"(N) : "memory");
}
__device__ __forceinline__ void ldm_x4(uint32_t* r, uint32_t addr) {
    asm volatile("ldmatrix.sync.aligned.m8n8.x4.shared.b16 {%0,%1,%2,%3}, [%4];"
        : "=r"(r[0]), "=r"(r[1]), "=r"(r[2]), "=r"(r[3]) : "r"(addr));
}
__device__ __forceinline__ void mma_f16(float* c, const uint32_t* a,
                                        uint32_t b0, uint32_t b1) {
    asm volatile(
        "mma.sync.aligned.m16n8k16.row.col.f32.f16.f16.f32 "
        "{%0,%1,%2,%3}, {%4,%5,%6,%7}, {%8,%9}, {%0,%1,%2,%3};"
        : "+f"(c[0]), "+f"(c[1]), "+f"(c[2]), "+f"(c[3])
        : "r"(a[0]), "r"(a[1]), "r"(a[2]), "r"(a[3]), "r"(b0), "r"(b1));
}

// ---------------- unified fp16 GEMM core -------------------------------------
// C = alpha * (Ah [+ Al]) · Bh^T.  CTA 128x128x32, 8 warps (2x4), warp 64x32.
// ASPLIT: 2-pass (Ah·Bh + Al·Bh). OUTM: 0=fp32, 1=fp16, 2=fp16 hi/lo split.
#define SKH   40
#define TILEH (128 * SKH * 2)   // 10240 B

__device__ __forceinline__ void load_tile_h(uint32_t dst, const h16* __restrict__ g,
                                            int ld, int k0, int tid)
{
    #pragma unroll
    for (int it = 0; it < 2; it++) {
        int idx = it * 256 + tid;
        int row = idx >> 2, ch = idx & 3;
        cp_async16(dst + (uint32_t)(row * SKH + ch * 8) * 2,
                   g + (size_t)row * ld + k0 + ch * 8);
    }
}

template<bool ASPLIT, int OUTM>
__device__ __forceinline__ void gemm_core(
    const h16* __restrict__ gAh, const h16* __restrict__ gAl,
    const h16* __restrict__ gBh, int lda, int ldb,
    float* __restrict__ Cf, h16* __restrict__ Ch, h16* __restrict__ Cl,
    int ldc, int klen, float alpha, char* smem)
{
    const int tid  = threadIdx.x;
    const int lane = tid & 31;
    const int w    = tid >> 5;
    const int wm   = (w & 1) * 64;
    const int wn   = (w >> 1) * 32;
    const uint32_t s32 = smem_to_u32(smem);
    constexpr uint32_t A_H = 0;
    constexpr uint32_t A_L = TILEH;
    constexpr uint32_t B_H = (ASPLIT ? 2 : 1) * TILEH;
    constexpr uint32_t STB = (ASPLIT ? 3 : 2) * TILEH;

    float acc[4][4][4];
    #pragma unroll
    for (int i = 0; i < 4; i++)
        #pragma unroll
        for (int j = 0; j < 4; j++)
            #pragma unroll
            for (int r = 0; r < 4; r++) acc[i][j][r] = 0.f;

    // stage 0
    load_tile_h(s32 + A_H, gAh, lda, 0, tid);
    if (ASPLIT) load_tile_h(s32 + A_L, gAl, lda, 0, tid);
    load_tile_h(s32 + B_H, gBh, ldb, 0, tid);
    CP_COMMIT();

    const int lr = lane & 15;
    const int lc = (lane >> 4) * 8;
    const int nkb = klen / 32;

    for (int kb = 0; kb < nkb; kb++) {
        if (kb + 1 < nkb) {
            uint32_t b = s32 + ((kb + 1) & 1) * STB;
            const int k0 = (kb + 1) * 32;
            load_tile_h(b + A_H, gAh, lda, k0, tid);
            if (ASPLIT) load_tile_h(b + A_L, gAl, lda, k0, tid);
            load_tile_h(b + B_H, gBh, ldb, k0, tid);
            CP_COMMIT();
            cp_wait<1>();
        } else {
            cp_wait<0>();
        }
        __syncthreads();
        const uint32_t base = s32 + (kb & 1) * STB;
        #pragma unroll
        for (int ki = 0; ki < 2; ki++) {
            uint32_t ah[4][4], al[4][4], bh[2][4];
            #pragma unroll
            for (int im = 0; im < 4; im++) {
                uint32_t off = (uint32_t)((wm + im*16 + lr) * SKH + ki*16 + lc) * 2;
                ldm_x4(ah[im], base + A_H + off);
                if (ASPLIT) ldm_x4(al[im], base + A_L + off);
            }
            #pragma unroll
            for (int g = 0; g < 2; g++) {
                uint32_t off = (uint32_t)((wn + g*16 + lr) * SKH + ki*16 + lc) * 2;
                ldm_x4(bh[g], base + B_H + off);
            }
            #pragma unroll
            for (int im = 0; im < 4; im++)
                #pragma unroll
                for (int in = 0; in < 4; in++) {
                    const int g = in >> 1, s = in & 1;
                    mma_f16(acc[im][in], ah[im], bh[g][s], bh[g][2+s]);
                    if (ASPLIT)
                        mma_f16(acc[im][in], al[im], bh[g][s], bh[g][2+s]);
                }
        }
        __syncthreads();
    }

    const int er = lane >> 2;
    const int ec = (lane & 3) * 2;
    #pragma unroll
    for (int im = 0; im < 4; im++)
        #pragma unroll
        for (int in = 0; in < 4; in++) {
            const int row0 = wm + im*16 + er;
            const int col  = wn + in*8 + ec;
            #pragma unroll
            for (int h = 0; h < 2; h++) {
                float v0 = acc[im][in][2*h + 0] * alpha;
                float v1 = acc[im][in][2*h + 1] * alpha;
                const size_t off = (size_t)(row0 + h*8) * ldc + col;
                if (OUTM == 0) {
                    float2 v = {v0, v1};
                    *reinterpret_cast<float2*>(Cf + off) = v;
                } else if (OUTM == 1) {
                    __half2 hh;
                    hh.x = __float2half_rn(v0);
                    hh.y = __float2half_rn(v1);
                    *reinterpret_cast<__half2*>(Ch + off) = hh;
                } else {
                    h16 h0 = __float2half_rn(v0);
                    h16 h1 = __float2half_rn(v1);
                    h16 l0 = __float2half_rn(v0 - __half2float(h0));
                    h16 l1 = __float2half_rn(v1 - __half2float(h1));
                    __half2 hp; hp.x = h0; hp.y = h1;
                    __half2 lp; lp.x = l0; lp.y = l1;
                    *reinterpret_cast<__half2*>(Ch + off) = hp;
                    *reinterpret_cast<__half2*>(Cl + off) = lp;
                }
            }
        }
}

// ---------------- GEMM kernels ------------------------------------------------
#define PROJ_SMEM (2 * 3 * TILEH)   // 61440
#define PV_SMEM   (2 * 2 * TILEH)   // 40960

__global__ __launch_bounds__(256)
void proj_kernel(const h16* __restrict__ Xh, const h16* __restrict__ Xl,
                 const h16* __restrict__ WkTh, h16* __restrict__ Kh,
                 const h16* __restrict__ Qh, const h16* __restrict__ Ql,
                 const h16* __restrict__ WqTh,
                 h16* __restrict__ QKh, h16* __restrict__ QKl)
{
    extern __shared__ char smem[];
    const int bn = blockIdx.x * 128;
    if (blockIdx.y < NN_/128) {
        const int bm = blockIdx.y * 128;
        gemm_core<true, 1>(
            Xh + (size_t)bm * DD_, Xl + (size_t)bm * DD_,
            WkTh + (size_t)bn * DD_, DD_, DD_,
            nullptr, Kh + (size_t)bm * DK_ + bn, nullptr,
            DK_, DD_, 1.f, smem);
    } else {
        const int bm = (blockIdx.y - NN_/128) * 128;
        gemm_core<true, 2>(
            Qh + (size_t)bm * DD_, Ql + (size_t)bm * DD_,
            WqTh + (size_t)bn * DD_, DD_, DD_,
            nullptr, QKh + (size_t)bm * DK_ + bn, QKl + (size_t)bm * DK_ + bn,
            DK_, DD_, 1.f, smem);
    }
}

__global__ __launch_bounds__(256)
void logits_kernel(const h16* __restrict__ QKh, const h16* __restrict__ QKl,
                   const h16* __restrict__ Kh, float* __restrict__ L)
{
    extern __shared__ char smem[];
    const int bn = blockIdx.x * 128;
    const int bm = blockIdx.y * 128;
    gemm_core<true, 0>(
        QKh + (size_t)bm * DK_, QKl + (size_t)bm * DK_,
        Kh + (size_t)bn * DK_, DK_, DK_,
        L + (size_t)bm * NN_ + bn, nullptr, nullptr,
        NN_, DK_, SCALE_, smem);
}

__global__ __launch_bounds__(256)
void pv_kernel(const h16* __restrict__ Ph, const h16* __restrict__ yTh,
               float* __restrict__ part)
{
    extern __shared__ char smem[];
    const int bn = blockIdx.x * 128;
    const int bm = blockIdx.y * 128;
    const int z  = blockIdx.z;
    const int kbeg = z * (NN_ / KSPLIT_PV);
    gemm_core<false, 0>(
        Ph + (size_t)bm * NN_ + kbeg, nullptr,
        yTh + (size_t)bn * NN_ + kbeg, NN_, NN_,
        part + (size_t)z * QQ_ * DV_ + (size_t)bm * DV_ + bn, nullptr, nullptr,
        DV_, NN_ / KSPLIT_PV, 1.f, smem);
}

// ---------------- prep: mask probe, splits, transposes ------------------------
__global__ void detect_mask_kernel(const unsigned int* __restrict__ mw)
{
    __shared__ int any;
    if (threadIdx.x == 0) any = 0;
    __syncthreads();
    int local = 0;
    for (int i = threadIdx.x; i < 4096; i += blockDim.x)
        if (mw[2 * i + 1] != 0u) local = 1;
    if (local) atomicOr(&any, 1);
    __syncthreads();
    if (threadIdx.x == 0) g_is64 = any ? 0 : 1;
}

#define SPLIT_BLKS ((NN_ + QQ_) * DD_ / 4 / 256)   // 12288
#define WTR_BLKS   1024                            // 2 x (16 x 32)
#define YTR_BLKS   2048                            // 8 x 256

__global__ __launch_bounds__(256)
void prep_all_kernel(const float* __restrict__ X, const float* __restrict__ Qx,
                     const float* __restrict__ Wk, const float* __restrict__ Wq,
                     const float* __restrict__ y,
                     h16* __restrict__ Xh, h16* __restrict__ Xl,
                     h16* __restrict__ Qh, h16* __restrict__ Ql,
                     h16* __restrict__ WkTh, h16* __restrict__ WqTh,
                     h16* __restrict__ yTh)
{
    __shared__ float tile[32][33];
    const int b   = blockIdx.x;
    const int tid = threadIdx.x;

    if (b < SPLIT_BLKS) {
        const int n4X = NN_ * DD_ / 4;
        int i = b * 256 + tid;
        const float* src; h16 *hi, *lo; int j;
        if (i < n4X) { src = X;  hi = Xh; lo = Xl; j = i; }
        else         { src = Qx; hi = Qh; lo = Ql; j = i - n4X; }
        float4 v = reinterpret_cast<const float4*>(src)[j];
        float f[4] = {v.x, v.y, v.z, v.w};
        h16 hh[4], ll[4];
        #pragma unroll
        for (int k = 0; k < 4; k++) {
            hh[k] = __float2half_rn(f[k]);
            ll[k] = __float2half_rn(f[k] - __half2float(hh[k]));
        }
        __half2 p0; p0.x = hh[0]; p0.y = hh[1];
        __half2 p1; p1.x = hh[2]; p1.y = hh[3];
        __half2 q0; q0.x = ll[0]; q0.y = ll[1];
        __half2 q1; q1.x = ll[2]; q1.y = ll[3];
        reinterpret_cast<__half2*>(hi)[2*j+0] = p0;
        reinterpret_cast<__half2*>(hi)[2*j+1] = p1;
        reinterpret_cast<__half2*>(lo)[2*j+0] = q0;
        reinterpret_cast<__half2*>(lo)[2*j+1] = q1;
        return;
    }

    const int tx = tid & 31, ty0 = tid >> 5;
    if (b < SPLIT_BLKS + WTR_BLKS) {
        // W transpose: [1024,512] -> WT fp16 [512,1024]
        int r = b - SPLIT_BLKS;
        const float* in = (r >= 512) ? Wq : Wk;
        h16* out = (r >= 512) ? WqTh : WkTh;
        r &= 511;
        const int cb = (r & 15) * 32;   // over DK_
        const int rb = (r >> 4) * 32;   // over DD_
        #pragma unroll
        for (int i = 0; i < 4; i++) {
            int ty = ty0 + i * 8;
            tile[ty][tx] = in[(size_t)(rb + ty) * DK_ + cb + tx];
        }
        __syncthreads();
        #pragma unroll
        for (int i = 0; i < 4; i++) {
            int ty = ty0 + i * 8;
            out[(size_t)(cb + ty) * DD_ + rb + tx] = __float2half_rn(tile[tx][ty]);
        }
    } else {
        // y transpose: [8192,256] -> yT fp16 [256,8192]
        int r = b - SPLIT_BLKS - WTR_BLKS;
        const int cb = (r & 7) * 32;    // over DV_
        const int rb = (r >> 3) * 32;   // over NN_
        #pragma unroll
        for (int i = 0; i < 4; i++) {
            int ty = ty0 + i * 8;
            tile[ty][tx] = y[(size_t)(rb + ty) * DV_ + cb + tx];
        }
        __syncthreads();
        #pragma unroll
        for (int i = 0; i < 4; i++) {
            int ty = ty0 + i * 8;
            yTh[(size_t)(cb + ty) * NN_ + rb + tx] = __float2half_rn(tile[tx][ty]);
        }
    }
}

// ---------------- masked softmax: fp32 logits -> fp16 probs -------------------
__device__ __forceinline__ float warpMax(float v) {
    #pragma unroll
    for (int o = 16; o; o >>= 1) v = fmaxf(v, __shfl_xor_sync(0xFFFFFFFFu, v, o));
    return v;
}
__device__ __forceinline__ float warpSum(float v) {
    #pragma unroll
    for (int o = 16; o; o >>= 1) v += __shfl_xor_sync(0xFFFFFFFFu, v, o);
    return v;
}

__global__ __launch_bounds__(256)
void masked_softmax_kernel(const float* __restrict__ L,
                           const unsigned int* __restrict__ mw,
                           h16* __restrict__ Ph)
{
    const int row  = blockIdx.x;
    const int tid  = threadIdx.x;
    const int lane = tid & 31, wid = tid >> 5;
    const int is64 = g_is64;

    const float4* Lv = reinterpret_cast<const float4*>(L + (size_t)row * NN_);
    const uint4*  M4 = reinterpret_cast<const uint4*>(mw);

    float4   xv[8];
    unsigned mk[8];
    float    mx = -FLT_MAX;

    #pragma unroll
    for (int i = 0; i < 8; i++) {
        const int idx = i * 256 + tid;
        float4 v = Lv[idx];
        unsigned m0, m1, m2, m3;
        if (is64) {
            uint4 a = M4[(size_t)row * 4096 + 2 * idx];
            uint4 b = M4[(size_t)row * 4096 + 2 * idx + 1];
            m0 = a.x | a.y; m1 = a.z | a.w; m2 = b.x | b.y; m3 = b.z | b.w;
        } else {
            uint4 a = M4[(size_t)row * 2048 + idx];
            m0 = a.x; m1 = a.y; m2 = a.z; m3 = a.w;
        }
        unsigned bits = (m0 ? 1u : 0u) | (m1 ? 2u : 0u) | (m2 ? 4u : 0u) | (m3 ? 8u : 0u);
        mk[i] = bits;
        xv[i] = v;
        if (bits & 1u) mx = fmaxf(mx, v.x);
        if (bits & 2u) mx = fmaxf(mx, v.y);
        if (bits & 4u) mx = fmaxf(mx, v.z);
        if (bits & 8u) mx = fmaxf(mx, v.w);
    }

    __shared__ float red[8];
    mx = warpMax(mx);
    if (lane == 0) red[wid] = mx;
    __syncthreads();
    if (wid == 0) {
        float t = (lane < 8) ? red[lane] : -FLT_MAX;
        t = warpMax(t);
        if (lane == 0) red[0] = t;
    }
    __syncthreads();
    mx = red[0];
    __syncthreads();

    float s = 0.f;
    #pragma unroll
    for (int i = 0; i < 8; i++) {
        float4 v = xv[i];
        v.x = (mk[i] & 1u) ? __expf(v.x - mx) : 0.f;
        v.y = (mk[i] & 2u) ? __expf(v.y - mx) : 0.f;
        v.z = (mk[i] & 4u) ? __expf(v.z - mx) : 0.f;
        v.w = (mk[i] & 8u) ? __expf(v.w - mx) : 0.f;
        s += v.x + v.y + v.z + v.w;
        xv[i] = v;
    }
    s = warpSum(s);
    if (lane == 0) red[wid] = s;
    __syncthreads();
    if (wid == 0) {
        float t = (lane < 8) ? red[lane] : 0.f;
        t = warpSum(t);
        if (lane == 0) red[0] = t;
    }
    __syncthreads();
    const float inv = (red[0] > 0.f) ? (1.f / red[0]) : 0.f;

    const size_t rowoff = (size_t)row * NN_;
    #pragma unroll
    for (int i = 0; i < 8; i++) {
        const int idx = i * 256 + tid;
        float4 v = xv[i];
        __half2 a, b;
        a.x = __float2half_rn(v.x * inv); a.y = __float2half_rn(v.y * inv);
        b.x = __float2half_rn(v.z * inv); b.y = __float2half_rn(v.w * inv);
        *reinterpret_cast<__half2*>(Ph + rowoff + idx * 4 + 0) = a;
        *reinterpret_cast<__half2*>(Ph + rowoff + idx * 4 + 2) = b;
    }
}

// ---------------- split-K reduction ------------------------------------------
__global__ __launch_bounds__(256)
void reduce16_kernel(const float* __restrict__ part, float* __restrict__ out)
{
    int i = blockIdx.x * 256 + threadIdx.x;
    const int n4 = QQ_ * DV_ / 4;
    if (i >= n4) return;
    const float4* p = reinterpret_cast<const float4*>(part);
    float4 acc = {0.f, 0.f, 0.f, 0.f};
    #pragma unroll
    for (int z = 0; z < KSPLIT_PV; z++) {
        float4 v = p[(size_t)z * n4 + i];
        acc.x += v.x; acc.y += v.y; acc.z += v.z; acc.w += v.w;
    }
    reinterpret_cast<float4*>(out)[i] = acc;
}

// ---------------- launch ------------------------------------------------------
extern "C" void kernel_launch(void* const* d_in, const int* in_sizes, int n_in,
                              void* d_out, int out_size)
{
    const float* search_x = nullptr;
    const float* search_y = nullptr;
    const float* query_x  = nullptr;
    const unsigned int* maskw = nullptr;
    const float* Wk = nullptr;
    const float* Wq = nullptr;

    for (int i = 0; i < n_in; i++) {
        long long sz = in_sizes[i];
        if      (sz == (long long)NN_ * DD_)  search_x = (const float*)d_in[i];
        else if (sz == (long long)NN_ * DV_)  search_y = (const float*)d_in[i];
        else if (sz == (long long)QQ_ * DD_)  query_x  = (const float*)d_in[i];
        else if (sz == (long long)QQ_ * NN_)  maskw    = (const unsigned int*)d_in[i];
        else if (sz == (long long)DD_ * DK_) { if (!Wk) Wk = (const float*)d_in[i];
                                               else      Wq = (const float*)d_in[i]; }
    }
    float* out = (float*)d_out;

    h16 *Xh,*Xl,*Qh,*Ql,*WkTh,*WqTh,*Kh,*QKh,*QKl,*Ph,*yTh;
    float *Lp, *Pp;
    cudaGetSymbolAddress((void**)&Xh,   g_Xhi);  cudaGetSymbolAddress((void**)&Xl,   g_Xlo);
    cudaGetSymbolAddress((void**)&Qh,   g_Qhi);  cudaGetSymbolAddress((void**)&Ql,   g_Qlo);
    cudaGetSymbolAddress((void**)&WkTh, g_WkTh); cudaGetSymbolAddress((void**)&WqTh, g_WqTh);
    cudaGetSymbolAddress((void**)&Kh,   g_Kh);
    cudaGetSymbolAddress((void**)&QKh,  g_QKh);  cudaGetSymbolAddress((void**)&QKl,  g_QKl);
    cudaGetSymbolAddress((void**)&Ph,   g_Ph);   cudaGetSymbolAddress((void**)&yTh,  g_yTh);
    cudaGetSymbolAddress((void**)&Lp,   g_L);    cudaGetSymbolAddress((void**)&Pp,   g_part);

    cudaFuncSetAttribute(proj_kernel,
        cudaFuncAttributeMaxDynamicSharedMemorySize, PROJ_SMEM);
    cudaFuncSetAttribute(logits_kernel,
        cudaFuncAttributeMaxDynamicSharedMemorySize, PROJ_SMEM);
    cudaFuncSetAttribute(pv_kernel,
        cudaFuncAttributeMaxDynamicSharedMemorySize, PV_SMEM);

    // 1) mask dtype probe
    detect_mask_kernel<<<1, 256>>>(maskw);
    // 2) all prep: split X/Q hi/lo, transpose W->fp16, transpose y->fp16
    prep_all_kernel<<<SPLIT_BLKS + WTR_BLKS + YTR_BLKS, 256>>>(
        search_x, query_x, Wk, Wq, search_y,
        Xh, Xl, Qh, Ql, WkTh, WqTh, yTh);
    // 3) fused projections: keys (fp16) & qk (fp16 hi/lo), 2-pass
    proj_kernel<<<dim3(DK_/128, NN_/128 + QQ_/128), 256, PROJ_SMEM>>>(
        Xh, Xl, WkTh, Kh, Qh, Ql, WqTh, QKh, QKl);
    // 4) logits = scale * (QKh+QKl) @ Kh^T -> fp32   [profiled launch]
    logits_kernel<<<dim3(NN_/128, QQ_/128), 256, PROJ_SMEM>>>(QKh, QKl, Kh, Lp);
    // 5) masked softmax -> fp16 P
    masked_softmax_kernel<<<QQ_, 256>>>(Lp, maskw, Ph);
    // 6) out partials = P @ y (1-pass fp16, split-K=16)
    pv_kernel<<<dim3(DV_/128, QQ_/128, KSPLIT_PV), 256, PV_SMEM>>>(Ph, yTh, Pp);
    // 7) reduce partials
    reduce16_kernel<<<(QQ_*DV_/4 + 255)/256, 256>>>(Pp, out);

    (void)out_size; (void)n_in;
}

// round 9
// speedup vs baseline: 1.7472x; 1.0325x over previous
#include <cuda_runtime.h>
#include <cuda_fp16.h>
#include <cstdint>
#include <float.h>

#define NN_  8192
#define DD_  1024
#define QQ_  4096
#define DK_  512
#define DV_  256
#define KSPLIT_PV 16
#define SCALE_  0.044194173824159216f

typedef __half h16;

// ---------------- scratch ----------------------------------------------------
__device__ h16 g_Xhi [(size_t)NN_*DD_], g_Xlo [(size_t)NN_*DD_];
__device__ h16 g_Qhi [(size_t)QQ_*DD_], g_Qlo [(size_t)QQ_*DD_];
__device__ h16 g_WkTh[(size_t)DK_*DD_];
__device__ h16 g_WqTh[(size_t)DK_*DD_];
__device__ h16 g_Kh  [(size_t)NN_*DK_];
__device__ h16 g_QKh [(size_t)QQ_*DK_], g_QKl[(size_t)QQ_*DK_];
__device__ float g_L [(size_t)QQ_*NN_];
__device__ h16 g_Ph  [(size_t)QQ_*NN_];
__device__ h16 g_yTh [(size_t)DV_*NN_];
__device__ float g_part[(size_t)KSPLIT_PV*QQ_*DV_];
__device__ int   g_is64;

// ---------------- base-ISA helpers -------------------------------------------
__device__ __forceinline__ uint32_t smem_to_u32(const void* p) {
    uint32_t a;
    asm("{ .reg .u64 t; cvta.to.shared.u64 t, %1; cvt.u32.u64 %0, t; }"
        : "=r"(a) : "l"(p));
    return a;
}
__device__ __forceinline__ void cp_async16(uint32_t dst, const void* src) {
    asm volatile("cp.async.cg.shared.global [%0], [%1], 16;" :: "r"(dst), "l"(src));
}
#define CP_COMMIT() asm volatile("cp.async.commit_group;" ::: "memory")
template<int N> __device__ __forceinline__ void cp_wait() {
    asm volatile("cp.async.wait_group %0;" :: "n"(N) : "memory");
}
__device__ __forceinline__ void ldm_x4(uint32_t* r, uint32_t addr) {
    asm volatile("ldmatrix.sync.aligned.m8n8.x4.shared.b16 {%0,%1,%2,%3}, [%4];"
        : "=r"(r[0]), "=r"(r[1]), "=r"(r[2]), "=r"(r[3]) : "r"(addr));
}
__device__ __forceinline__ void mma_f16(float* c, const uint32_t* a,
                                        uint32_t b0, uint32_t b1) {
    asm volatile(
        "mma.sync.aligned.m16n8k16.row.col.f32.f16.f16.f32 "
        "{%0,%1,%2,%3}, {%4,%5,%6,%7}, {%8,%9}, {%0,%1,%2,%3};"
        : "+f"(c[0]), "+f"(c[1]), "+f"(c[2]), "+f"(c[3])
        : "r"(a[0]), "r"(a[1]), "r"(a[2]), "r"(a[3]), "r"(b0), "r"(b1));
}

// ---------------- unified fp16 GEMM core (3-stage pipeline) -------------------
// C = alpha * (Ah [+ Al]) · Bh^T.  CTA 128x128x32, 8 warps (2x4), warp 64x32.
// ASPLIT: 2-pass (Ah·Bh + Al·Bh). OUTM: 0=fp32, 1=fp16, 2=fp16 hi/lo split.
#define SKH    40
#define TILEH  (128 * SKH * 2)   // 10240 B
#define NSTAGE 3

__device__ __forceinline__ void load_tile_h(uint32_t dst, const h16* __restrict__ g,
                                            int ld, int k0, int tid)
{
    #pragma unroll
    for (int it = 0; it < 2; it++) {
        int idx = it * 256 + tid;
        int row = idx >> 2, ch = idx & 3;
        cp_async16(dst + (uint32_t)(row * SKH + ch * 8) * 2,
                   g + (size_t)row * ld + k0 + ch * 8);
    }
}

template<bool ASPLIT, int OUTM>
__device__ __forceinline__ void gemm_core(
    const h16* __restrict__ gAh, const h16* __restrict__ gAl,
    const h16* __restrict__ gBh, int lda, int ldb,
    float* __restrict__ Cf, h16* __restrict__ Ch, h16* __restrict__ Cl,
    int ldc, int klen, float alpha, char* smem)
{
    const int tid  = threadIdx.x;
    const int lane = tid & 31;
    const int w    = tid >> 5;
    const int wm   = (w & 1) * 64;
    const int wn   = (w >> 1) * 32;
    const uint32_t s32 = smem_to_u32(smem);
    constexpr uint32_t A_H = 0;
    constexpr uint32_t A_L = TILEH;
    constexpr uint32_t B_H = (ASPLIT ? 2 : 1) * TILEH;
    constexpr uint32_t STB = (ASPLIT ? 3 : 2) * TILEH;

    float acc[4][4][4];
    #pragma unroll
    for (int i = 0; i < 4; i++)
        #pragma unroll
        for (int j = 0; j < 4; j++)
            #pragma unroll
            for (int r = 0; r < 4; r++) acc[i][j][r] = 0.f;

    // prologue: stages 0 and 1
    #pragma unroll
    for (int s = 0; s < NSTAGE - 1; s++) {
        uint32_t b = s32 + s * STB;
        load_tile_h(b + A_H, gAh, lda, s * 32, tid);
        if (ASPLIT) load_tile_h(b + A_L, gAl, lda, s * 32, tid);
        load_tile_h(b + B_H, gBh, ldb, s * 32, tid);
        CP_COMMIT();
    }

    const int lr = lane & 15;
    const int lc = (lane >> 4) * 8;
    const int nkb = klen / 32;
    int buf = 0;

    for (int kb = 0; kb < nkb; kb++) {
        cp_wait<NSTAGE - 2>();
        __syncthreads();

        // prefetch kb+2 into the buffer consumed at iteration kb-1
        {
            int pb = buf + (NSTAGE - 1); if (pb >= NSTAGE) pb -= NSTAGE;
            if (kb + NSTAGE - 1 < nkb) {
                uint32_t b = s32 + pb * STB;
                const int k0 = (kb + NSTAGE - 1) * 32;
                load_tile_h(b + A_H, gAh, lda, k0, tid);
                if (ASPLIT) load_tile_h(b + A_L, gAl, lda, k0, tid);
                load_tile_h(b + B_H, gBh, ldb, k0, tid);
            }
            CP_COMMIT();
        }

        const uint32_t base = s32 + buf * STB;
        #pragma unroll
        for (int ki = 0; ki < 2; ki++) {
            uint32_t ah[4][4], al[4][4], bh[2][4];
            #pragma unroll
            for (int im = 0; im < 4; im++) {
                uint32_t off = (uint32_t)((wm + im*16 + lr) * SKH + ki*16 + lc) * 2;
                ldm_x4(ah[im], base + A_H + off);
                if (ASPLIT) ldm_x4(al[im], base + A_L + off);
            }
            #pragma unroll
            for (int g = 0; g < 2; g++) {
                uint32_t off = (uint32_t)((wn + g*16 + lr) * SKH + ki*16 + lc) * 2;
                ldm_x4(bh[g], base + B_H + off);
            }
            #pragma unroll
            for (int im = 0; im < 4; im++)
                #pragma unroll
                for (int in = 0; in < 4; in++) {
                    const int g = in >> 1, s = in & 1;
                    mma_f16(acc[im][in], ah[im], bh[g][s], bh[g][2+s]);
                    if (ASPLIT)
                        mma_f16(acc[im][in], al[im], bh[g][s], bh[g][2+s]);
                }
        }
        buf++; if (buf == NSTAGE) buf = 0;
    }

    const int er = lane >> 2;
    const int ec = (lane & 3) * 2;
    #pragma unroll
    for (int im = 0; im < 4; im++)
        #pragma unroll
        for (int in = 0; in < 4; in++) {
            const int row0 = wm + im*16 + er;
            const int col  = wn + in*8 + ec;
            #pragma unroll
            for (int h = 0; h < 2; h++) {
                float v0 = acc[im][in][2*h + 0] * alpha;
                float v1 = acc[im][in][2*h + 1] * alpha;
                const size_t off = (size_t)(row0 + h*8) * ldc + col;
                if (OUTM == 0) {
                    float2 v = {v0, v1};
                    *reinterpret_cast<float2*>(Cf + off) = v;
                } else if (OUTM == 1) {
                    __half2 hh;
                    hh.x = __float2half_rn(v0);
                    hh.y = __float2half_rn(v1);
                    *reinterpret_cast<__half2*>(Ch + off) = hh;
                } else {
                    h16 h0 = __float2half_rn(v0);
                    h16 h1 = __float2half_rn(v1);
                    h16 l0 = __float2half_rn(v0 - __half2float(h0));
                    h16 l1 = __float2half_rn(v1 - __half2float(h1));
                    __half2 hp; hp.x = h0; hp.y = h1;
                    __half2 lp; lp.x = l0; lp.y = l1;
                    *reinterpret_cast<__half2*>(Ch + off) = hp;
                    *reinterpret_cast<__half2*>(Cl + off) = lp;
                }
            }
        }
}

// ---------------- GEMM kernels ------------------------------------------------
#define PROJ_SMEM (NSTAGE * 3 * TILEH)   // 92160
#define PV_SMEM   (NSTAGE * 2 * TILEH)   // 61440

__global__ __launch_bounds__(256)
void proj_kernel(const h16* __restrict__ Xh, const h16* __restrict__ Xl,
                 const h16* __restrict__ WkTh, h16* __restrict__ Kh,
                 const h16* __restrict__ Qh, const h16* __restrict__ Ql,
                 const h16* __restrict__ WqTh,
                 h16* __restrict__ QKh, h16* __restrict__ QKl)
{
    extern __shared__ char smem[];
    const int bn = blockIdx.x * 128;
    if (blockIdx.y < NN_/128) {
        const int bm = blockIdx.y * 128;
        gemm_core<true, 1>(
            Xh + (size_t)bm * DD_, Xl + (size_t)bm * DD_,
            WkTh + (size_t)bn * DD_, DD_, DD_,
            nullptr, Kh + (size_t)bm * DK_ + bn, nullptr,
            DK_, DD_, 1.f, smem);
    } else {
        const int bm = (blockIdx.y - NN_/128) * 128;
        gemm_core<true, 2>(
            Qh + (size_t)bm * DD_, Ql + (size_t)bm * DD_,
            WqTh + (size_t)bn * DD_, DD_, DD_,
            nullptr, QKh + (size_t)bm * DK_ + bn, QKl + (size_t)bm * DK_ + bn,
            DK_, DD_, 1.f, smem);
    }
}

__global__ __launch_bounds__(256)
void logits_kernel(const h16* __restrict__ QKh, const h16* __restrict__ QKl,
                   const h16* __restrict__ Kh, float* __restrict__ L)
{
    extern __shared__ char smem[];
    const int bn = blockIdx.x * 128;
    const int bm = blockIdx.y * 128;
    gemm_core<true, 0>(
        QKh + (size_t)bm * DK_, QKl + (size_t)bm * DK_,
        Kh + (size_t)bn * DK_, DK_, DK_,
        L + (size_t)bm * NN_ + bn, nullptr, nullptr,
        NN_, DK_, SCALE_, smem);
}

__global__ __launch_bounds__(256)
void pv_kernel(const h16* __restrict__ Ph, const h16* __restrict__ yTh,
               float* __restrict__ part)
{
    extern __shared__ char smem[];
    const int bn = blockIdx.x * 128;
    const int bm = blockIdx.y * 128;
    const int z  = blockIdx.z;
    const int kbeg = z * (NN_ / KSPLIT_PV);
    gemm_core<false, 0>(
        Ph + (size_t)bm * NN_ + kbeg, nullptr,
        yTh + (size_t)bn * NN_ + kbeg, NN_, NN_,
        part + (size_t)z * QQ_ * DV_ + (size_t)bm * DV_ + bn, nullptr, nullptr,
        DV_, NN_ / KSPLIT_PV, 1.f, smem);
}

// ---------------- prep: mask probe, splits, transposes ------------------------
__global__ void detect_mask_kernel(const unsigned int* __restrict__ mw)
{
    __shared__ int any;
    if (threadIdx.x == 0) any = 0;
    __syncthreads();
    int local = 0;
    for (int i = threadIdx.x; i < 4096; i += blockDim.x)
        if (mw[2 * i + 1] != 0u) local = 1;
    if (local) atomicOr(&any, 1);
    __syncthreads();
    if (threadIdx.x == 0) g_is64 = any ? 0 : 1;
}

#define SPLIT_BLKS ((NN_ + QQ_) * DD_ / 4 / 256)   // 12288
#define WTR_BLKS   1024
#define YTR_BLKS   2048

__global__ __launch_bounds__(256)
void prep_all_kernel(const float* __restrict__ X, const float* __restrict__ Qx,
                     const float* __restrict__ Wk, const float* __restrict__ Wq,
                     const float* __restrict__ y,
                     h16* __restrict__ Xh, h16* __restrict__ Xl,
                     h16* __restrict__ Qh, h16* __restrict__ Ql,
                     h16* __restrict__ WkTh, h16* __restrict__ WqTh,
                     h16* __restrict__ yTh)
{
    __shared__ float tile[32][33];
    const int b   = blockIdx.x;
    const int tid = threadIdx.x;

    if (b < SPLIT_BLKS) {
        const int n4X = NN_ * DD_ / 4;
        int i = b * 256 + tid;
        const float* src; h16 *hi, *lo; int j;
        if (i < n4X) { src = X;  hi = Xh; lo = Xl; j = i; }
        else         { src = Qx; hi = Qh; lo = Ql; j = i - n4X; }
        float4 v = reinterpret_cast<const float4*>(src)[j];
        float f[4] = {v.x, v.y, v.z, v.w};
        h16 hh[4], ll[4];
        #pragma unroll
        for (int k = 0; k < 4; k++) {
            hh[k] = __float2half_rn(f[k]);
            ll[k] = __float2half_rn(f[k] - __half2float(hh[k]));
        }
        __half2 p0; p0.x = hh[0]; p0.y = hh[1];
        __half2 p1; p1.x = hh[2]; p1.y = hh[3];
        __half2 q0; q0.x = ll[0]; q0.y = ll[1];
        __half2 q1; q1.x = ll[2]; q1.y = ll[3];
        reinterpret_cast<__half2*>(hi)[2*j+0] = p0;
        reinterpret_cast<__half2*>(hi)[2*j+1] = p1;
        reinterpret_cast<__half2*>(lo)[2*j+0] = q0;
        reinterpret_cast<__half2*>(lo)[2*j+1] = q1;
        return;
    }

    const int tx = tid & 31, ty0 = tid >> 5;
    if (b < SPLIT_BLKS + WTR_BLKS) {
        int r = b - SPLIT_BLKS;
        const float* in = (r >= 512) ? Wq : Wk;
        h16* out = (r >= 512) ? WqTh : WkTh;
        r &= 511;
        const int cb = (r & 15) * 32;
        const int rb = (r >> 4) * 32;
        #pragma unroll
        for (int i = 0; i < 4; i++) {
            int ty = ty0 + i * 8;
            tile[ty][tx] = in[(size_t)(rb + ty) * DK_ + cb + tx];
        }
        __syncthreads();
        #pragma unroll
        for (int i = 0; i < 4; i++) {
            int ty = ty0 + i * 8;
            out[(size_t)(cb + ty) * DD_ + rb + tx] = __float2half_rn(tile[tx][ty]);
        }
    } else {
        int r = b - SPLIT_BLKS - WTR_BLKS;
        const int cb = (r & 7) * 32;
        const int rb = (r >> 3) * 32;
        #pragma unroll
        for (int i = 0; i < 4; i++) {
            int ty = ty0 + i * 8;
            tile[ty][tx] = y[(size_t)(rb + ty) * DV_ + cb + tx];
        }
        __syncthreads();
        #pragma unroll
        for (int i = 0; i < 4; i++) {
            int ty = ty0 + i * 8;
            yTh[(size_t)(cb + ty) * NN_ + rb + tx] = __float2half_rn(tile[tx][ty]);
        }
    }
}

// ---------------- masked softmax ---------------------------------------------
__device__ __forceinline__ float warpMax(float v) {
    #pragma unroll
    for (int o = 16; o; o >>= 1) v = fmaxf(v, __shfl_xor_sync(0xFFFFFFFFu, v, o));
    return v;
}
__device__ __forceinline__ float warpSum(float v) {
    #pragma unroll
    for (int o = 16; o; o >>= 1) v += __shfl_xor_sync(0xFFFFFFFFu, v, o);
    return v;
}

__global__ __launch_bounds__(256)
void masked_softmax_kernel(const float* __restrict__ L,
                           const unsigned int* __restrict__ mw,
                           h16* __restrict__ Ph)
{
    const int row  = blockIdx.x;
    const int tid  = threadIdx.x;
    const int lane = tid & 31, wid = tid >> 5;
    const int is64 = g_is64;

    const float4* Lv = reinterpret_cast<const float4*>(L + (size_t)row * NN_);
    const uint4*  M4 = reinterpret_cast<const uint4*>(mw);

    float4   xv[8];
    unsigned mk[8];
    float    mx = -FLT_MAX;

    #pragma unroll
    for (int i = 0; i < 8; i++) {
        const int idx = i * 256 + tid;
        float4 v = Lv[idx];
        unsigned m0, m1, m2, m3;
        if (is64) {
            uint4 a = M4[(size_t)row * 4096 + 2 * idx];
            uint4 b = M4[(size_t)row * 4096 + 2 * idx + 1];
            m0 = a.x | a.y; m1 = a.z | a.w; m2 = b.x | b.y; m3 = b.z | b.w;
        } else {
            uint4 a = M4[(size_t)row * 2048 + idx];
            m0 = a.x; m1 = a.y; m2 = a.z; m3 = a.w;
        }
        unsigned bits = (m0 ? 1u : 0u) | (m1 ? 2u : 0u) | (m2 ? 4u : 0u) | (m3 ? 8u : 0u);
        mk[i] = bits;
        xv[i] = v;
        if (bits & 1u) mx = fmaxf(mx, v.x);
        if (bits & 2u) mx = fmaxf(mx, v.y);
        if (bits & 4u) mx = fmaxf(mx, v.z);
        if (bits & 8u) mx = fmaxf(mx, v.w);
    }

    __shared__ float red[8];
    mx = warpMax(mx);
    if (lane == 0) red[wid] = mx;
    __syncthreads();
    if (wid == 0) {
        float t = (lane < 8) ? red[lane] : -FLT_MAX;
        t = warpMax(t);
        if (lane == 0) red[0] = t;
    }
    __syncthreads();
    mx = red[0];
    __syncthreads();

    float s = 0.f;
    #pragma unroll
    for (int i = 0; i < 8; i++) {
        float4 v = xv[i];
        v.x = (mk[i] & 1u) ? __expf(v.x - mx) : 0.f;
        v.y = (mk[i] & 2u) ? __expf(v.y - mx) : 0.f;
        v.z = (mk[i] & 4u) ? __expf(v.z - mx) : 0.f;
        v.w = (mk[i] & 8u) ? __expf(v.w - mx) : 0.f;
        s += v.x + v.y + v.z + v.w;
        xv[i] = v;
    }
    s = warpSum(s);
    if (lane == 0) red[wid] = s;
    __syncthreads();
    if (wid == 0) {
        float t = (lane < 8) ? red[lane] : 0.f;
        t = warpSum(t);
        if (lane == 0) red[0] = t;
    }
    __syncthreads();
    const float inv = (red[0] > 0.f) ? (1.f / red[0]) : 0.f;

    const size_t rowoff = (size_t)row * NN_;
    #pragma unroll
    for (int i = 0; i < 8; i++) {
        const int idx = i * 256 + tid;
        float4 v = xv[i];
        __half2 a, b;
        a.x = __float2half_rn(v.x * inv); a.y = __float2half_rn(v.y * inv);
        b.x = __float2half_rn(v.z * inv); b.y = __float2half_rn(v.w * inv);
        *reinterpret_cast<__half2*>(Ph + rowoff + idx * 4 + 0) = a;
        *reinterpret_cast<__half2*>(Ph + rowoff + idx * 4 + 2) = b;
    }
}

// ---------------- split-K reduction ------------------------------------------
__global__ __launch_bounds__(256)
void reduce16_kernel(const float* __restrict__ part, float* __restrict__ out)
{
    int i = blockIdx.x * 256 + threadIdx.x;
    const int n4 = QQ_ * DV_ / 4;
    if (i >= n4) return;
    const float4* p = reinterpret_cast<const float4*>(part);
    float4 acc = {0.f, 0.f, 0.f, 0.f};
    #pragma unroll
    for (int z = 0; z < KSPLIT_PV; z++) {
        float4 v = p[(size_t)z * n4 + i];
        acc.x += v.x; acc.y += v.y; acc.z += v.z; acc.w += v.w;
    }
    reinterpret_cast<float4*>(out)[i] = acc;
}

// ---------------- launch ------------------------------------------------------
extern "C" void kernel_launch(void* const* d_in, const int* in_sizes, int n_in,
                              void* d_out, int out_size)
{
    const float* search_x = nullptr;
    const float* search_y = nullptr;
    const float* query_x  = nullptr;
    const unsigned int* maskw = nullptr;
    const float* Wk = nullptr;
    const float* Wq = nullptr;

    for (int i = 0; i < n_in; i++) {
        long long sz = in_sizes[i];
        if      (sz == (long long)NN_ * DD_)  search_x = (const float*)d_in[i];
        else if (sz == (long long)NN_ * DV_)  search_y = (const float*)d_in[i];
        else if (sz == (long long)QQ_ * DD_)  query_x  = (const float*)d_in[i];
        else if (sz == (long long)QQ_ * NN_)  maskw    = (const unsigned int*)d_in[i];
        else if (sz == (long long)DD_ * DK_) { if (!Wk) Wk = (const float*)d_in[i];
                                               else      Wq = (const float*)d_in[i]; }
    }
    float* out = (float*)d_out;

    h16 *Xh,*Xl,*Qh,*Ql,*WkTh,*WqTh,*Kh,*QKh,*QKl,*Ph,*yTh;
    float *Lp, *Pp;
    cudaGetSymbolAddress((void**)&Xh,   g_Xhi);  cudaGetSymbolAddress((void**)&Xl,   g_Xlo);
    cudaGetSymbolAddress((void**)&Qh,   g_Qhi);  cudaGetSymbolAddress((void**)&Ql,   g_Qlo);
    cudaGetSymbolAddress((void**)&WkTh, g_WkTh); cudaGetSymbolAddress((void**)&WqTh, g_WqTh);
    cudaGetSymbolAddress((void**)&Kh,   g_Kh);
    cudaGetSymbolAddress((void**)&QKh,  g_QKh);  cudaGetSymbolAddress((void**)&QKl,  g_QKl);
    cudaGetSymbolAddress((void**)&Ph,   g_Ph);   cudaGetSymbolAddress((void**)&yTh,  g_yTh);
    cudaGetSymbolAddress((void**)&Lp,   g_L);    cudaGetSymbolAddress((void**)&Pp,   g_part);

    cudaFuncSetAttribute(proj_kernel,
        cudaFuncAttributeMaxDynamicSharedMemorySize, PROJ_SMEM);
    cudaFuncSetAttribute(logits_kernel,
        cudaFuncAttributeMaxDynamicSharedMemorySize, PROJ_SMEM);
    cudaFuncSetAttribute(pv_kernel,
        cudaFuncAttributeMaxDynamicSharedMemorySize, PV_SMEM);

    // 1) mask dtype probe
    detect_mask_kernel<<<1, 256>>>(maskw);
    // 2) all prep
    prep_all_kernel<<<SPLIT_BLKS + WTR_BLKS + YTR_BLKS, 256>>>(
        search_x, query_x, Wk, Wq, search_y,
        Xh, Xl, Qh, Ql, WkTh, WqTh, yTh);
    // 3) fused projections
    proj_kernel<<<dim3(DK_/128, NN_/128 + QQ_/128), 256, PROJ_SMEM>>>(
        Xh, Xl, WkTh, Kh, Qh, Ql, WqTh, QKh, QKl);
    // 4) logits (profiled launch)
    logits_kernel<<<dim3(NN_/128, QQ_/128), 256, PROJ_SMEM>>>(QKh, QKl, Kh, Lp);
    // 5) masked softmax -> fp16 P
    masked_softmax_kernel<<<QQ_, 256>>>(Lp, maskw, Ph);
    // 6) PV partials (1-pass fp16, split-K=16)
    pv_kernel<<<dim3(DV_/128, QQ_/128, KSPLIT_PV), 256, PV_SMEM>>>(Ph, yTh, Pp);
    // 7) reduce
    reduce16_kernel<<<(QQ_*DV_/4 + 255)/256, 256>>>(Pp, out);

    (void)out_size; (void)n_in;
}

// round 10
// speedup vs baseline: 1.8406x; 1.0534x over previous
#include <cuda_runtime.h>
#include <cuda_fp16.h>
#include <cstdint>
#include <float.h>

#define NN_  8192
#define DD_  1024
#define QQ_  4096
#define DK_  512
#define DV_  256
#define KSPLIT_PV 16
#define SCALE_  0.044194173824159216f

typedef __half h16;

// ---------------- scratch ----------------------------------------------------
__device__ h16 g_Xhi [(size_t)NN_*DD_], g_Xlo [(size_t)NN_*DD_];
__device__ h16 g_Qhi [(size_t)QQ_*DD_], g_Qlo [(size_t)QQ_*DD_];
__device__ h16 g_WkTh[(size_t)DK_*DD_];
__device__ h16 g_WqTh[(size_t)DK_*DD_];
__device__ h16 g_Kh  [(size_t)NN_*DK_];
__device__ h16 g_QKh [(size_t)QQ_*DK_], g_QKl[(size_t)QQ_*DK_];
__device__ h16 g_Lh  [(size_t)QQ_*NN_];            // fp16 logits (64 MB)
__device__ h16 g_Ph  [(size_t)QQ_*NN_];
__device__ h16 g_yTh [(size_t)DV_*NN_];
__device__ float g_part[(size_t)KSPLIT_PV*QQ_*DV_];
__device__ int   g_is64;

// ---------------- base-ISA helpers -------------------------------------------
__device__ __forceinline__ uint32_t smem_to_u32(const void* p) {
    uint32_t a;
    asm("{ .reg .u64 t; cvta.to.shared.u64 t, %1; cvt.u32.u64 %0, t; }"
        : "=r"(a) : "l"(p));
    return a;
}
__device__ __forceinline__ void cp_async16(uint32_t dst, const void* src) {
    asm volatile("cp.async.cg.shared.global [%0], [%1], 16;" :: "r"(dst), "l"(src));
}
#define CP_COMMIT() asm volatile("cp.async.commit_group;" ::: "memory")
template<int N> __device__ __forceinline__ void cp_wait() {
    asm volatile("cp.async.wait_group %0;" :: "n"(N) : "memory");
}
__device__ __forceinline__ void ldm_x4(uint32_t* r, uint32_t addr) {
    asm volatile("ldmatrix.sync.aligned.m8n8.x4.shared.b16 {%0,%1,%2,%3}, [%4];"
        : "=r"(r[0]), "=r"(r[1]), "=r"(r[2]), "=r"(r[3]) : "r"(addr));
}
__device__ __forceinline__ void mma_f16(float* c, const uint32_t* a,
                                        uint32_t b0, uint32_t b1) {
    asm volatile(
        "mma.sync.aligned.m16n8k16.row.col.f32.f16.f16.f32 "
        "{%0,%1,%2,%3}, {%4,%5,%6,%7}, {%8,%9}, {%0,%1,%2,%3};"
        : "+f"(c[0]), "+f"(c[1]), "+f"(c[2]), "+f"(c[3])
        : "r"(a[0]), "r"(a[1]), "r"(a[2]), "r"(a[3]), "r"(b0), "r"(b1));
}

// ---------------- unified fp16 GEMM core (3-stage, warp tile 32x64) ----------
// C = alpha * (Ah [+ Al]) · Bh^T.  CTA 128x128x32, 8 warps as 4x2 grid.
// ASPLIT: 2-pass. OUTM: 0=fp32, 1=fp16, 2=fp16 hi/lo split.
#define SKH    40
#define TILEH  (128 * SKH * 2)   // 10240 B
#define NSTAGE 3

__device__ __forceinline__ void load_tile_h(uint32_t dst, const h16* __restrict__ g,
                                            int ld, int k0, int tid)
{
    #pragma unroll
    for (int it = 0; it < 2; it++) {
        int idx = it * 256 + tid;
        int row = idx >> 2, ch = idx & 3;
        cp_async16(dst + (uint32_t)(row * SKH + ch * 8) * 2,
                   g + (size_t)row * ld + k0 + ch * 8);
    }
}

template<bool ASPLIT, int OUTM>
__device__ __forceinline__ void gemm_core(
    const h16* __restrict__ gAh, const h16* __restrict__ gAl,
    const h16* __restrict__ gBh, int lda, int ldb,
    float* __restrict__ Cf, h16* __restrict__ Ch, h16* __restrict__ Cl,
    int ldc, int klen, float alpha, char* smem)
{
    const int tid  = threadIdx.x;
    const int lane = tid & 31;
    const int w    = tid >> 5;
    const int wm   = (w & 3) * 32;     // 4 warps along M
    const int wn   = (w >> 2) * 64;    // 2 warps along N
    const uint32_t s32 = smem_to_u32(smem);
    constexpr uint32_t A_H = 0;
    constexpr uint32_t A_L = TILEH;
    constexpr uint32_t B_H = (ASPLIT ? 2 : 1) * TILEH;
    constexpr uint32_t STB = (ASPLIT ? 3 : 2) * TILEH;

    float acc[2][8][4];
    #pragma unroll
    for (int i = 0; i < 2; i++)
        #pragma unroll
        for (int j = 0; j < 8; j++)
            #pragma unroll
            for (int r = 0; r < 4; r++) acc[i][j][r] = 0.f;

    #pragma unroll
    for (int s = 0; s < NSTAGE - 1; s++) {
        uint32_t b = s32 + s * STB;
        load_tile_h(b + A_H, gAh, lda, s * 32, tid);
        if (ASPLIT) load_tile_h(b + A_L, gAl, lda, s * 32, tid);
        load_tile_h(b + B_H, gBh, ldb, s * 32, tid);
        CP_COMMIT();
    }

    const int lr = lane & 15;
    const int lc = (lane >> 4) * 8;
    const int nkb = klen / 32;
    int buf = 0;

    for (int kb = 0; kb < nkb; kb++) {
        cp_wait<NSTAGE - 2>();
        __syncthreads();

        {
            int pb = buf + (NSTAGE - 1); if (pb >= NSTAGE) pb -= NSTAGE;
            if (kb + NSTAGE - 1 < nkb) {
                uint32_t b = s32 + pb * STB;
                const int k0 = (kb + NSTAGE - 1) * 32;
                load_tile_h(b + A_H, gAh, lda, k0, tid);
                if (ASPLIT) load_tile_h(b + A_L, gAl, lda, k0, tid);
                load_tile_h(b + B_H, gBh, ldb, k0, tid);
            }
            CP_COMMIT();
        }

        const uint32_t base = s32 + buf * STB;
        #pragma unroll
        for (int ki = 0; ki < 2; ki++) {
            uint32_t ah[2][4], al[2][4], bh[4][4];
            #pragma unroll
            for (int im = 0; im < 2; im++) {
                uint32_t off = (uint32_t)((wm + im*16 + lr) * SKH + ki*16 + lc) * 2;
                ldm_x4(ah[im], base + A_H + off);
                if (ASPLIT) ldm_x4(al[im], base + A_L + off);
            }
            #pragma unroll
            for (int g = 0; g < 4; g++) {
                uint32_t off = (uint32_t)((wn + g*16 + lr) * SKH + ki*16 + lc) * 2;
                ldm_x4(bh[g], base + B_H + off);
            }
            #pragma unroll
            for (int im = 0; im < 2; im++)
                #pragma unroll
                for (int in = 0; in < 8; in++) {
                    const int g = in >> 1, s = in & 1;
                    mma_f16(acc[im][in], ah[im], bh[g][s], bh[g][2+s]);
                    if (ASPLIT)
                        mma_f16(acc[im][in], al[im], bh[g][s], bh[g][2+s]);
                }
        }
        buf++; if (buf == NSTAGE) buf = 0;
    }

    const int er = lane >> 2;
    const int ec = (lane & 3) * 2;
    #pragma unroll
    for (int im = 0; im < 2; im++)
        #pragma unroll
        for (int in = 0; in < 8; in++) {
            const int row0 = wm + im*16 + er;
            const int col  = wn + in*8 + ec;
            #pragma unroll
            for (int h = 0; h < 2; h++) {
                float v0 = acc[im][in][2*h + 0] * alpha;
                float v1 = acc[im][in][2*h + 1] * alpha;
                const size_t off = (size_t)(row0 + h*8) * ldc + col;
                if (OUTM == 0) {
                    float2 v = {v0, v1};
                    *reinterpret_cast<float2*>(Cf + off) = v;
                } else if (OUTM == 1) {
                    *reinterpret_cast<__half2*>(Ch + off) =
                        __floats2half2_rn(v0, v1);
                } else {
                    h16 h0 = __float2half_rn(v0);
                    h16 h1 = __float2half_rn(v1);
                    h16 l0 = __float2half_rn(v0 - __half2float(h0));
                    h16 l1 = __float2half_rn(v1 - __half2float(h1));
                    __half2 hp; hp.x = h0; hp.y = h1;
                    __half2 lp; lp.x = l0; lp.y = l1;
                    *reinterpret_cast<__half2*>(Ch + off) = hp;
                    *reinterpret_cast<__half2*>(Cl + off) = lp;
                }
            }
        }
}

// ---------------- GEMM kernels ------------------------------------------------
#define PROJ_SMEM (NSTAGE * 3 * TILEH)   // 92160
#define PV_SMEM   (NSTAGE * 2 * TILEH)   // 61440

__global__ __launch_bounds__(256, 2)
void proj_kernel(const h16* __restrict__ Xh, const h16* __restrict__ Xl,
                 const h16* __restrict__ WkTh, h16* __restrict__ Kh,
                 const h16* __restrict__ Qh, const h16* __restrict__ Ql,
                 const h16* __restrict__ WqTh,
                 h16* __restrict__ QKh, h16* __restrict__ QKl)
{
    extern __shared__ char smem[];
    const int bn = blockIdx.x * 128;
    if (blockIdx.y < NN_/128) {
        const int bm = blockIdx.y * 128;
        gemm_core<true, 1>(
            Xh + (size_t)bm * DD_, Xl + (size_t)bm * DD_,
            WkTh + (size_t)bn * DD_, DD_, DD_,
            nullptr, Kh + (size_t)bm * DK_ + bn, nullptr,
            DK_, DD_, 1.f, smem);
    } else {
        const int bm = (blockIdx.y - NN_/128) * 128;
        gemm_core<true, 2>(
            Qh + (size_t)bm * DD_, Ql + (size_t)bm * DD_,
            WqTh + (size_t)bn * DD_, DD_, DD_,
            nullptr, QKh + (size_t)bm * DK_ + bn, QKl + (size_t)bm * DK_ + bn,
            DK_, DD_, 1.f, smem);
    }
}

__global__ __launch_bounds__(256, 2)
void logits_kernel(const h16* __restrict__ QKh, const h16* __restrict__ QKl,
                   const h16* __restrict__ Kh, h16* __restrict__ Lh)
{
    extern __shared__ char smem[];
    const int bn = blockIdx.x * 128;
    const int bm = blockIdx.y * 128;
    gemm_core<true, 1>(
        QKh + (size_t)bm * DK_, QKl + (size_t)bm * DK_,
        Kh + (size_t)bn * DK_, DK_, DK_,
        nullptr, Lh + (size_t)bm * NN_ + bn, nullptr,
        NN_, DK_, SCALE_, smem);
}

__global__ __launch_bounds__(256, 2)
void pv_kernel(const h16* __restrict__ Ph, const h16* __restrict__ yTh,
               float* __restrict__ part)
{
    extern __shared__ char smem[];
    const int bn = blockIdx.x * 128;
    const int bm = blockIdx.y * 128;
    const int z  = blockIdx.z;
    const int kbeg = z * (NN_ / KSPLIT_PV);
    gemm_core<false, 0>(
        Ph + (size_t)bm * NN_ + kbeg, nullptr,
        yTh + (size_t)bn * NN_ + kbeg, NN_, NN_,
        part + (size_t)z * QQ_ * DV_ + (size_t)bm * DV_ + bn, nullptr, nullptr,
        DV_, NN_ / KSPLIT_PV, 1.f, smem);
}

// ---------------- prep --------------------------------------------------------
__global__ void detect_mask_kernel(const unsigned int* __restrict__ mw)
{
    __shared__ int any;
    if (threadIdx.x == 0) any = 0;
    __syncthreads();
    int local = 0;
    for (int i = threadIdx.x; i < 4096; i += blockDim.x)
        if (mw[2 * i + 1] != 0u) local = 1;
    if (local) atomicOr(&any, 1);
    __syncthreads();
    if (threadIdx.x == 0) g_is64 = any ? 0 : 1;
}

#define SPLIT_BLKS ((NN_ + QQ_) * DD_ / 4 / 256)   // 12288
#define WTR_BLKS   1024
#define YTR_BLKS   2048

__global__ __launch_bounds__(256)
void prep_all_kernel(const float* __restrict__ X, const float* __restrict__ Qx,
                     const float* __restrict__ Wk, const float* __restrict__ Wq,
                     const float* __restrict__ y,
                     h16* __restrict__ Xh, h16* __restrict__ Xl,
                     h16* __restrict__ Qh, h16* __restrict__ Ql,
                     h16* __restrict__ WkTh, h16* __restrict__ WqTh,
                     h16* __restrict__ yTh)
{
    __shared__ float tile[32][33];
    const int b   = blockIdx.x;
    const int tid = threadIdx.x;

    if (b < SPLIT_BLKS) {
        const int n4X = NN_ * DD_ / 4;
        int i = b * 256 + tid;
        const float* src; h16 *hi, *lo; int j;
        if (i < n4X) { src = X;  hi = Xh; lo = Xl; j = i; }
        else         { src = Qx; hi = Qh; lo = Ql; j = i - n4X; }
        float4 v = reinterpret_cast<const float4*>(src)[j];
        float f[4] = {v.x, v.y, v.z, v.w};
        h16 hh[4], ll[4];
        #pragma unroll
        for (int k = 0; k < 4; k++) {
            hh[k] = __float2half_rn(f[k]);
            ll[k] = __float2half_rn(f[k] - __half2float(hh[k]));
        }
        __half2 p0; p0.x = hh[0]; p0.y = hh[1];
        __half2 p1; p1.x = hh[2]; p1.y = hh[3];
        __half2 q0; q0.x = ll[0]; q0.y = ll[1];
        __half2 q1; q1.x = ll[2]; q1.y = ll[3];
        reinterpret_cast<__half2*>(hi)[2*j+0] = p0;
        reinterpret_cast<__half2*>(hi)[2*j+1] = p1;
        reinterpret_cast<__half2*>(lo)[2*j+0] = q0;
        reinterpret_cast<__half2*>(lo)[2*j+1] = q1;
        return;
    }

    const int tx = tid & 31, ty0 = tid >> 5;
    if (b < SPLIT_BLKS + WTR_BLKS) {
        int r = b - SPLIT_BLKS;
        const float* in = (r >= 512) ? Wq : Wk;
        h16* out = (r >= 512) ? WqTh : WkTh;
        r &= 511;
        const int cb = (r & 15) * 32;
        const int rb = (r >> 4) * 32;
        #pragma unroll
        for (int i = 0; i < 4; i++) {
            int ty = ty0 + i * 8;
            tile[ty][tx] = in[(size_t)(rb + ty) * DK_ + cb + tx];
        }
        __syncthreads();
        #pragma unroll
        for (int i = 0; i < 4; i++) {
            int ty = ty0 + i * 8;
            out[(size_t)(cb + ty) * DD_ + rb + tx] = __float2half_rn(tile[tx][ty]);
        }
    } else {
        int r = b - SPLIT_BLKS - WTR_BLKS;
        const int cb = (r & 7) * 32;
        const int rb = (r >> 3) * 32;
        #pragma unroll
        for (int i = 0; i < 4; i++) {
            int ty = ty0 + i * 8;
            tile[ty][tx] = y[(size_t)(rb + ty) * DV_ + cb + tx];
        }
        __syncthreads();
        #pragma unroll
        for (int i = 0; i < 4; i++) {
            int ty = ty0 + i * 8;
            yTh[(size_t)(cb + ty) * NN_ + rb + tx] = __float2half_rn(tile[tx][ty]);
        }
    }
}

// ---------------- masked softmax: fp16 logits -> fp16 probs -------------------
__device__ __forceinline__ float warpMax(float v) {
    #pragma unroll
    for (int o = 16; o; o >>= 1) v = fmaxf(v, __shfl_xor_sync(0xFFFFFFFFu, v, o));
    return v;
}
__device__ __forceinline__ float warpSum(float v) {
    #pragma unroll
    for (int o = 16; o; o >>= 1) v += __shfl_xor_sync(0xFFFFFFFFu, v, o);
    return v;
}

__global__ __launch_bounds__(256)
void masked_softmax_kernel(const h16* __restrict__ Lh,
                           const unsigned int* __restrict__ mw,
                           h16* __restrict__ Ph)
{
    const int row  = blockIdx.x;
    const int tid  = threadIdx.x;
    const int lane = tid & 31, wid = tid >> 5;
    const int is64 = g_is64;

    const uint4* Lv = reinterpret_cast<const uint4*>(Lh + (size_t)row * NN_);
    const uint4* M4 = reinterpret_cast<const uint4*>(mw);

    float    f[32];
    unsigned mkw = 0;      // bit e set = element active
    float    mx = -FLT_MAX;

    #pragma unroll
    for (int i = 0; i < 4; i++) {
        const int idx = i * 256 + tid;   // uint4 (8 halves) index in row
        uint4 v = Lv[idx];
        const __half2* hp = reinterpret_cast<const __half2*>(&v);
        #pragma unroll
        for (int j = 0; j < 4; j++) {
            float2 fv = __half22float2(hp[j]);
            f[i*8 + 2*j + 0] = fv.x;
            f[i*8 + 2*j + 1] = fv.y;
        }
        if (is64) {
            #pragma unroll
            for (int q = 0; q < 4; q++) {
                uint4 a = M4[(size_t)row * 4096 + idx * 4 + q];
                if (a.x | a.y) mkw |= 1u << (i*8 + q*2 + 0);
                if (a.z | a.w) mkw |= 1u << (i*8 + q*2 + 1);
            }
        } else {
            #pragma unroll
            for (int q = 0; q < 2; q++) {
                uint4 a = M4[(size_t)row * 2048 + idx * 2 + q];
                if (a.x) mkw |= 1u << (i*8 + q*4 + 0);
                if (a.y) mkw |= 1u << (i*8 + q*4 + 1);
                if (a.z) mkw |= 1u << (i*8 + q*4 + 2);
                if (a.w) mkw |= 1u << (i*8 + q*4 + 3);
            }
        }
    }
    #pragma unroll
    for (int e = 0; e < 32; e++)
        if (mkw & (1u << e)) mx = fmaxf(mx, f[e]);

    __shared__ float red[8];
    mx = warpMax(mx);
    if (lane == 0) red[wid] = mx;
    __syncthreads();
    if (wid == 0) {
        float t = (lane < 8) ? red[lane] : -FLT_MAX;
        t = warpMax(t);
        if (lane == 0) red[0] = t;
    }
    __syncthreads();
    mx = red[0];
    __syncthreads();

    float s = 0.f;
    #pragma unroll
    for (int e = 0; e < 32; e++) {
        float p = (mkw & (1u << e)) ? __expf(f[e] - mx) : 0.f;
        f[e] = p;
        s += p;
    }
    s = warpSum(s);
    if (lane == 0) red[wid] = s;
    __syncthreads();
    if (wid == 0) {
        float t = (lane < 8) ? red[lane] : 0.f;
        t = warpSum(t);
        if (lane == 0) red[0] = t;
    }
    __syncthreads();
    const float inv = (red[0] > 0.f) ? (1.f / red[0]) : 0.f;

    uint4* Pv = reinterpret_cast<uint4*>(Ph + (size_t)row * NN_);
    #pragma unroll
    for (int i = 0; i < 4; i++) {
        const int idx = i * 256 + tid;
        uint4 o;
        __half2* hp = reinterpret_cast<__half2*>(&o);
        #pragma unroll
        for (int j = 0; j < 4; j++)
            hp[j] = __floats2half2_rn(f[i*8 + 2*j] * inv, f[i*8 + 2*j + 1] * inv);
        Pv[idx] = o;
    }
}

// ---------------- split-K reduction ------------------------------------------
__global__ __launch_bounds__(256)
void reduce16_kernel(const float* __restrict__ part, float* __restrict__ out)
{
    int i = blockIdx.x * 256 + threadIdx.x;
    const int n4 = QQ_ * DV_ / 4;
    if (i >= n4) return;
    const float4* p = reinterpret_cast<const float4*>(part);
    float4 acc = {0.f, 0.f, 0.f, 0.f};
    #pragma unroll
    for (int z = 0; z < KSPLIT_PV; z++) {
        float4 v = p[(size_t)z * n4 + i];
        acc.x += v.x; acc.y += v.y; acc.z += v.z; acc.w += v.w;
    }
    reinterpret_cast<float4*>(out)[i] = acc;
}

// ---------------- launch ------------------------------------------------------
extern "C" void kernel_launch(void* const* d_in, const int* in_sizes, int n_in,
                              void* d_out, int out_size)
{
    const float* search_x = nullptr;
    const float* search_y = nullptr;
    const float* query_x  = nullptr;
    const unsigned int* maskw = nullptr;
    const float* Wk = nullptr;
    const float* Wq = nullptr;

    for (int i = 0; i < n_in; i++) {
        long long sz = in_sizes[i];
        if      (sz == (long long)NN_ * DD_)  search_x = (const float*)d_in[i];
        else if (sz == (long long)NN_ * DV_)  search_y = (const float*)d_in[i];
        else if (sz == (long long)QQ_ * DD_)  query_x  = (const float*)d_in[i];
        else if (sz == (long long)QQ_ * NN_)  maskw    = (const unsigned int*)d_in[i];
        else if (sz == (long long)DD_ * DK_) { if (!Wk) Wk = (const float*)d_in[i];
                                               else      Wq = (const float*)d_in[i]; }
    }
    float* out = (float*)d_out;

    h16 *Xh,*Xl,*Qh,*Ql,*WkTh,*WqTh,*Kh,*QKh,*QKl,*Lh,*Ph,*yTh;
    float *Pp;
    cudaGetSymbolAddress((void**)&Xh,   g_Xhi);  cudaGetSymbolAddress((void**)&Xl,   g_Xlo);
    cudaGetSymbolAddress((void**)&Qh,   g_Qhi);  cudaGetSymbolAddress((void**)&Ql,   g_Qlo);
    cudaGetSymbolAddress((void**)&WkTh, g_WkTh); cudaGetSymbolAddress((void**)&WqTh, g_WqTh);
    cudaGetSymbolAddress((void**)&Kh,   g_Kh);
    cudaGetSymbolAddress((void**)&QKh,  g_QKh);  cudaGetSymbolAddress((void**)&QKl,  g_QKl);
    cudaGetSymbolAddress((void**)&Lh,   g_Lh);   cudaGetSymbolAddress((void**)&Ph,   g_Ph);
    cudaGetSymbolAddress((void**)&yTh,  g_yTh);  cudaGetSymbolAddress((void**)&Pp,   g_part);

    cudaFuncSetAttribute(proj_kernel,
        cudaFuncAttributeMaxDynamicSharedMemorySize, PROJ_SMEM);
    cudaFuncSetAttribute(logits_kernel,
        cudaFuncAttributeMaxDynamicSharedMemorySize, PROJ_SMEM);
    cudaFuncSetAttribute(pv_kernel,
        cudaFuncAttributeMaxDynamicSharedMemorySize, PV_SMEM);

    // 1) mask dtype probe
    detect_mask_kernel<<<1, 256>>>(maskw);
    // 2) all prep
    prep_all_kernel<<<SPLIT_BLKS + WTR_BLKS + YTR_BLKS, 256>>>(
        search_x, query_x, Wk, Wq, search_y,
        Xh, Xl, Qh, Ql, WkTh, WqTh, yTh);
    // 3) fused projections
    proj_kernel<<<dim3(DK_/128, NN_/128 + QQ_/128), 256, PROJ_SMEM>>>(
        Xh, Xl, WkTh, Kh, Qh, Ql, WqTh, QKh, QKl);
    // 4) logits -> fp16 (profiled launch)
    logits_kernel<<<dim3(NN_/128, QQ_/128), 256, PROJ_SMEM>>>(QKh, QKl, Kh, Lh);
    // 5) masked softmax -> fp16 P
    masked_softmax_kernel<<<QQ_, 256>>>(Lh, maskw, Ph);
    // 6) PV partials (1-pass fp16, split-K=16)
    pv_kernel<<<dim3(DV_/128, QQ_/128, KSPLIT_PV), 256, PV_SMEM>>>(Ph, yTh, Pp);
    // 7) reduce
    reduce16_kernel<<<(QQ_*DV_/4 + 255)/256, 256>>>(Pp, out);

    (void)out_size; (void)n_in;
}